// round 1
// baseline (speedup 1.0000x reference)
#include <cuda_runtime.h>

#define S_LEN 2048
#define BATCH 2
#define DM    1024
#define NHEAD 16
#define DKH   64
#define DFF   4096
#define NTOK  (BATCH * S_LEN)   // 4096
#define LN_EPS 1e-6f

// ---------------- scratch (device globals; no allocation) ----------------
__device__ float g_n1[NTOK * DM];   // LN1 output
__device__ float g_q [NTOK * DM];
__device__ float g_k [NTOK * DM];
__device__ float g_v [NTOK * DM];
__device__ float g_ao[NTOK * DM];   // attention output (pre-Wo)
__device__ float g_h [NTOK * DM];   // residual after attention block
__device__ float g_n2[NTOK * DM];   // LN2 output
__device__ float g_f1[NTOK * DFF];  // FFN hidden

// ---------------- LayerNorm (unbiased variance, scalar alpha/beta) -------
__global__ void __launch_bounds__(256) ln_kernel(
    const float* __restrict__ x, const float* __restrict__ alpha,
    const float* __restrict__ beta, float* __restrict__ y)
{
    int row = blockIdx.x;
    int tid = threadIdx.x;
    const float4* x4 = (const float4*)(x + (size_t)row * DM);
    float4 v = x4[tid];                       // 256 threads * 4 = 1024
    float s = v.x + v.y + v.z + v.w;
    float q = v.x * v.x + v.y * v.y + v.z * v.z + v.w * v.w;

    __shared__ float rs[8], rq[8];
#pragma unroll
    for (int o = 16; o; o >>= 1) {
        s += __shfl_xor_sync(0xffffffffu, s, o);
        q += __shfl_xor_sync(0xffffffffu, q, o);
    }
    if ((tid & 31) == 0) { rs[tid >> 5] = s; rq[tid >> 5] = q; }
    __syncthreads();
    s = 0.f; q = 0.f;
#pragma unroll
    for (int i = 0; i < 8; i++) { s += rs[i]; q += rq[i]; }

    float mean = s * (1.0f / DM);
    float var  = (q - (float)DM * mean * mean) * (1.0f / (DM - 1));  // ddof=1
    float a    = alpha[0];
    float b    = beta[0];
    float inv  = a / (sqrtf(var) + LN_EPS);

    float4 o;
    o.x = (v.x - mean) * inv + b;
    o.y = (v.y - mean) * inv + b;
    o.z = (v.z - mean) * inv + b;
    o.w = (v.w - mean) * inv + b;
    ((float4*)(y + (size_t)row * DM))[tid] = o;
}

// ---------------- GEMM: C = A[M,K] @ B[K,N] + bias (+res) (+relu) --------
// 128x128 tile, BK=16, 256 threads, 8x8 per thread (two 4x4 quads per dim)
template<bool RELU, bool RES>
__global__ void __launch_bounds__(256, 2) gemm_kernel(
    const float* __restrict__ A, const float* __restrict__ B,
    const float* __restrict__ bias, const float* __restrict__ res,
    float* __restrict__ C, int M, int N, int K)
{
    __shared__ float As[16][128];   // As[k][m]
    __shared__ float Bs[16][128];   // Bs[k][n]

    int tid = threadIdx.x;
    int tx = tid & 15;              // n-direction (16)
    int ty = tid >> 4;              // m-direction (16)

    const float* Ap = A + (size_t)blockIdx.y * 128 * K;
    const float* Bp = B + (size_t)blockIdx.x * 128;

    float acc[8][8];
#pragma unroll
    for (int i = 0; i < 8; i++)
#pragma unroll
        for (int j = 0; j < 8; j++) acc[i][j] = 0.f;

    for (int k0 = 0; k0 < K; k0 += 16) {
        // A tile: 128 rows x 16 cols = 512 float4 loads / 256 threads
#pragma unroll
        for (int i = 0; i < 2; i++) {
            int f = tid * 2 + i;
            int r = f >> 2, c = (f & 3) << 2;
            float4 v = *(const float4*)(Ap + (size_t)r * K + k0 + c);
            As[c + 0][r] = v.x; As[c + 1][r] = v.y;
            As[c + 2][r] = v.z; As[c + 3][r] = v.w;
        }
        // B tile: 16 rows x 128 cols
#pragma unroll
        for (int i = 0; i < 2; i++) {
            int f = tid * 2 + i;
            int r = f >> 5, c = (f & 31) << 2;
            *(float4*)&Bs[r][c] = *(const float4*)(Bp + (size_t)(k0 + r) * N + c);
        }
        __syncthreads();

#pragma unroll
        for (int kk = 0; kk < 16; kk++) {
            float ar[8], br[8];
            float4 t;
            t = *(const float4*)&As[kk][ty * 4];
            ar[0] = t.x; ar[1] = t.y; ar[2] = t.z; ar[3] = t.w;
            t = *(const float4*)&As[kk][64 + ty * 4];
            ar[4] = t.x; ar[5] = t.y; ar[6] = t.z; ar[7] = t.w;
            t = *(const float4*)&Bs[kk][tx * 4];
            br[0] = t.x; br[1] = t.y; br[2] = t.z; br[3] = t.w;
            t = *(const float4*)&Bs[kk][64 + tx * 4];
            br[4] = t.x; br[5] = t.y; br[6] = t.z; br[7] = t.w;
#pragma unroll
            for (int i = 0; i < 8; i++)
#pragma unroll
                for (int j = 0; j < 8; j++)
                    acc[i][j] += ar[i] * br[j];
        }
        __syncthreads();
    }

    int rowb = blockIdx.y * 128;
    int colb = blockIdx.x * 128;
#pragma unroll
    for (int i = 0; i < 8; i++) {
        int row = rowb + ((i < 4) ? (ty * 4 + i) : (64 + ty * 4 + (i - 4)));
#pragma unroll
        for (int jq = 0; jq < 2; jq++) {
            int col = colb + ((jq == 0) ? (tx * 4) : (64 + tx * 4));
            float4 o;
            o.x = acc[i][jq * 4 + 0] + bias[col + 0];
            o.y = acc[i][jq * 4 + 1] + bias[col + 1];
            o.z = acc[i][jq * 4 + 2] + bias[col + 2];
            o.w = acc[i][jq * 4 + 3] + bias[col + 3];
            if (RES) {
                float4 r4 = *(const float4*)(res + (size_t)row * N + col);
                o.x += r4.x; o.y += r4.y; o.z += r4.z; o.w += r4.w;
            }
            if (RELU) {
                o.x = fmaxf(o.x, 0.f); o.y = fmaxf(o.y, 0.f);
                o.z = fmaxf(o.z, 0.f); o.w = fmaxf(o.w, 0.f);
            }
            *(float4*)(C + (size_t)row * N + col) = o;
        }
    }
}

// ---------------- Attention: one block per (query, head, batch) ----------
// Scores over all 2048 keys in smem, block softmax (NO 1/sqrt(dk) scaling),
// then coalesced V accumulation.
__global__ void __launch_bounds__(256) attn_kernel(
    const float* __restrict__ Q, const float* __restrict__ K,
    const float* __restrict__ V, float* __restrict__ O)
{
    int qi = blockIdx.x, h = blockIdx.y, b = blockIdx.z;
    int tid = threadIdx.x;

    __shared__ float qs[DKH];
    __shared__ float sc[S_LEN];
    __shared__ float red[8];
    __shared__ float part[4][DKH];

    const float* qrow = Q + ((size_t)(b * S_LEN + qi)) * DM + h * DKH;
    if (tid < DKH) qs[tid] = qrow[tid];
    __syncthreads();

    // scores
    const float* Kb = K + (size_t)b * S_LEN * DM + h * DKH;
    const float4* q4 = (const float4*)qs;
    for (int k = tid; k < S_LEN; k += 256) {
        const float4* kr = (const float4*)(Kb + (size_t)k * DM);
        float s = 0.f;
#pragma unroll
        for (int d = 0; d < 16; d++) {
            float4 kv = kr[d], qv = q4[d];
            s += kv.x * qv.x + kv.y * qv.y + kv.z * qv.z + kv.w * qv.w;
        }
        sc[k] = s;
    }
    __syncthreads();

    // max
    float m = -1e30f;
    for (int k = tid; k < S_LEN; k += 256) m = fmaxf(m, sc[k]);
#pragma unroll
    for (int o = 16; o; o >>= 1) m = fmaxf(m, __shfl_xor_sync(0xffffffffu, m, o));
    if ((tid & 31) == 0) red[tid >> 5] = m;
    __syncthreads();
    m = red[0];
#pragma unroll
    for (int i = 1; i < 8; i++) m = fmaxf(m, red[i]);

    // exp + sum
    float sum = 0.f;
    for (int k = tid; k < S_LEN; k += 256) {
        float e = __expf(sc[k] - m);
        sc[k] = e;
        sum += e;
    }
#pragma unroll
    for (int o = 16; o; o >>= 1) sum += __shfl_xor_sync(0xffffffffu, sum, o);
    __syncthreads();                 // red reads done; sc writes visible
    if ((tid & 31) == 0) red[tid >> 5] = sum;
    __syncthreads();
    sum = 0.f;
#pragma unroll
    for (int i = 0; i < 8; i++) sum += red[i];
    float inv = 1.0f / sum;

    // output: d = tid&63, 4 key chunks of 512
    int d = tid & 63, chunk = tid >> 6;
    const float* Vb = V + (size_t)b * S_LEN * DM + h * DKH + d;
    float acc = 0.f;
    int k0 = chunk * 512;
    for (int k = k0; k < k0 + 512; k++)
        acc += sc[k] * Vb[(size_t)k * DM];
    part[chunk][d] = acc;
    __syncthreads();
    if (tid < DKH) {
        float o = (part[0][tid] + part[1][tid] + part[2][tid] + part[3][tid]) * inv;
        O[((size_t)(b * S_LEN + qi)) * DM + h * DKH + tid] = o;
    }
}

// ---------------- launch ----------------
extern "C" void kernel_launch(void* const* d_in, const int* in_sizes, int n_in,
                              void* d_out, int out_size)
{
    const float* x    = (const float*)d_in[0];
    const float* Wq   = (const float*)d_in[1];
    const float* bq   = (const float*)d_in[2];
    const float* Wk   = (const float*)d_in[3];
    const float* bk   = (const float*)d_in[4];
    const float* Wv   = (const float*)d_in[5];
    const float* bv   = (const float*)d_in[6];
    const float* Wo   = (const float*)d_in[7];
    const float* bo   = (const float*)d_in[8];
    const float* W1   = (const float*)d_in[9];
    const float* b1   = (const float*)d_in[10];
    const float* W2   = (const float*)d_in[11];
    const float* b2   = (const float*)d_in[12];
    const float* ln1a = (const float*)d_in[13];
    const float* ln1b = (const float*)d_in[14];
    const float* ln2a = (const float*)d_in[15];
    const float* ln2b = (const float*)d_in[16];
    float* out = (float*)d_out;

    float *p_n1, *p_q, *p_k, *p_v, *p_ao, *p_h, *p_n2, *p_f1;
    cudaGetSymbolAddress((void**)&p_n1, g_n1);
    cudaGetSymbolAddress((void**)&p_q,  g_q);
    cudaGetSymbolAddress((void**)&p_k,  g_k);
    cudaGetSymbolAddress((void**)&p_v,  g_v);
    cudaGetSymbolAddress((void**)&p_ao, g_ao);
    cudaGetSymbolAddress((void**)&p_h,  g_h);
    cudaGetSymbolAddress((void**)&p_n2, g_n2);
    cudaGetSymbolAddress((void**)&p_f1, g_f1);

    // 1) LN1
    ln_kernel<<<NTOK, 256>>>(x, ln1a, ln1b, p_n1);

    // 2) Q/K/V projections
    dim3 gP(DM / 128, NTOK / 128);                // (8, 32)
    gemm_kernel<false, false><<<gP, 256>>>(p_n1, Wq, bq, nullptr, p_q, NTOK, DM, DM);
    gemm_kernel<false, false><<<gP, 256>>>(p_n1, Wk, bk, nullptr, p_k, NTOK, DM, DM);
    gemm_kernel<false, false><<<gP, 256>>>(p_n1, Wv, bv, nullptr, p_v, NTOK, DM, DM);

    // 3) attention (no scaling, per reference)
    attn_kernel<<<dim3(S_LEN, NHEAD, BATCH), 256>>>(p_q, p_k, p_v, p_ao);

    // 4) output projection + residual(x)
    gemm_kernel<false, true><<<gP, 256>>>(p_ao, Wo, bo, x, p_h, NTOK, DM, DM);

    // 5) LN2
    ln_kernel<<<NTOK, 256>>>(p_h, ln2a, ln2b, p_n2);

    // 6) FFN up + ReLU
    gemm_kernel<true, false><<<dim3(DFF / 128, NTOK / 128), 256>>>(
        p_n2, W1, b1, nullptr, p_f1, NTOK, DFF, DM);

    // 7) FFN down + residual(h) -> out
    gemm_kernel<false, true><<<dim3(DM / 128, NTOK / 128), 256>>>(
        p_f1, W2, b2, p_h, out, NTOK, DM, DFF);
}

// round 2
// speedup vs baseline: 3.4711x; 3.4711x over previous
#include <cuda_runtime.h>
#include <math.h>

#define S_LEN 2048
#define BATCH 2
#define DM    1024
#define NHEAD 16
#define DKH   64
#define DFF   4096
#define NTOK  (BATCH * S_LEN)   // 4096
#define LN_EPS 1e-6f

// flash-attn tiling
#define ABM 128   // queries per block
#define ABN 64    // keys per tile

// ---------------- scratch (device globals; no allocation) ----------------
__device__ float g_n1[NTOK * DM];   // LN1 output
__device__ float g_q [NTOK * DM];
__device__ float g_k [NTOK * DM];
__device__ float g_v [NTOK * DM];
__device__ float g_ao[NTOK * DM];   // attention output (pre-Wo)
__device__ float g_h [NTOK * DM];   // residual after attention block
__device__ float g_n2[NTOK * DM];   // LN2 output
__device__ float g_f1[NTOK * DFF];  // FFN hidden

// ---------------- LayerNorm (unbiased variance, scalar alpha/beta) -------
__global__ void __launch_bounds__(256) ln_kernel(
    const float* __restrict__ x, const float* __restrict__ alpha,
    const float* __restrict__ beta, float* __restrict__ y)
{
    int row = blockIdx.x;
    int tid = threadIdx.x;
    const float4* x4 = (const float4*)(x + (size_t)row * DM);
    float4 v = x4[tid];
    float s = v.x + v.y + v.z + v.w;
    float q = v.x * v.x + v.y * v.y + v.z * v.z + v.w * v.w;

    __shared__ float rs[8], rq[8];
#pragma unroll
    for (int o = 16; o; o >>= 1) {
        s += __shfl_xor_sync(0xffffffffu, s, o);
        q += __shfl_xor_sync(0xffffffffu, q, o);
    }
    if ((tid & 31) == 0) { rs[tid >> 5] = s; rq[tid >> 5] = q; }
    __syncthreads();
    s = 0.f; q = 0.f;
#pragma unroll
    for (int i = 0; i < 8; i++) { s += rs[i]; q += rq[i]; }

    float mean = s * (1.0f / DM);
    float var  = (q - (float)DM * mean * mean) * (1.0f / (DM - 1));  // ddof=1
    float a    = alpha[0];
    float b    = beta[0];
    float inv  = a / (sqrtf(var) + LN_EPS);

    float4 o;
    o.x = (v.x - mean) * inv + b;
    o.y = (v.y - mean) * inv + b;
    o.z = (v.z - mean) * inv + b;
    o.w = (v.w - mean) * inv + b;
    ((float4*)(y + (size_t)row * DM))[tid] = o;
}

// ---------------- GEMM: C = A[M,K] @ B[K,N] + bias (+res) (+relu) --------
template<bool RELU, bool RES>
__global__ void __launch_bounds__(256, 2) gemm_kernel(
    const float* __restrict__ A, const float* __restrict__ B,
    const float* __restrict__ bias, const float* __restrict__ res,
    float* __restrict__ C, int M, int N, int K)
{
    __shared__ float As[16][128];   // As[k][m]
    __shared__ float Bs[16][128];   // Bs[k][n]

    int tid = threadIdx.x;
    int tx = tid & 15;
    int ty = tid >> 4;

    const float* Ap = A + (size_t)blockIdx.y * 128 * K;
    const float* Bp = B + (size_t)blockIdx.x * 128;

    float acc[8][8];
#pragma unroll
    for (int i = 0; i < 8; i++)
#pragma unroll
        for (int j = 0; j < 8; j++) acc[i][j] = 0.f;

    for (int k0 = 0; k0 < K; k0 += 16) {
#pragma unroll
        for (int i = 0; i < 2; i++) {
            int f = tid * 2 + i;
            int r = f >> 2, c = (f & 3) << 2;
            float4 v = *(const float4*)(Ap + (size_t)r * K + k0 + c);
            As[c + 0][r] = v.x; As[c + 1][r] = v.y;
            As[c + 2][r] = v.z; As[c + 3][r] = v.w;
        }
#pragma unroll
        for (int i = 0; i < 2; i++) {
            int f = tid * 2 + i;
            int r = f >> 5, c = (f & 31) << 2;
            *(float4*)&Bs[r][c] = *(const float4*)(Bp + (size_t)(k0 + r) * N + c);
        }
        __syncthreads();

#pragma unroll
        for (int kk = 0; kk < 16; kk++) {
            float ar[8], br[8];
            float4 t;
            t = *(const float4*)&As[kk][ty * 4];
            ar[0] = t.x; ar[1] = t.y; ar[2] = t.z; ar[3] = t.w;
            t = *(const float4*)&As[kk][64 + ty * 4];
            ar[4] = t.x; ar[5] = t.y; ar[6] = t.z; ar[7] = t.w;
            t = *(const float4*)&Bs[kk][tx * 4];
            br[0] = t.x; br[1] = t.y; br[2] = t.z; br[3] = t.w;
            t = *(const float4*)&Bs[kk][64 + tx * 4];
            br[4] = t.x; br[5] = t.y; br[6] = t.z; br[7] = t.w;
#pragma unroll
            for (int i = 0; i < 8; i++)
#pragma unroll
                for (int j = 0; j < 8; j++)
                    acc[i][j] += ar[i] * br[j];
        }
        __syncthreads();
    }

    int rowb = blockIdx.y * 128;
    int colb = blockIdx.x * 128;
#pragma unroll
    for (int i = 0; i < 8; i++) {
        int row = rowb + ((i < 4) ? (ty * 4 + i) : (64 + ty * 4 + (i - 4)));
#pragma unroll
        for (int jq = 0; jq < 2; jq++) {
            int col = colb + ((jq == 0) ? (tx * 4) : (64 + tx * 4));
            float4 o;
            o.x = acc[i][jq * 4 + 0] + bias[col + 0];
            o.y = acc[i][jq * 4 + 1] + bias[col + 1];
            o.z = acc[i][jq * 4 + 2] + bias[col + 2];
            o.w = acc[i][jq * 4 + 3] + bias[col + 3];
            if (RES) {
                float4 r4 = *(const float4*)(res + (size_t)row * N + col);
                o.x += r4.x; o.y += r4.y; o.z += r4.z; o.w += r4.w;
            }
            if (RELU) {
                o.x = fmaxf(o.x, 0.f); o.y = fmaxf(o.y, 0.f);
                o.z = fmaxf(o.z, 0.f); o.w = fmaxf(o.w, 0.f);
            }
            *(float4*)(C + (size_t)row * N + col) = o;
        }
    }
}

// ---------------- Flash attention (fp32 SIMT, online softmax) ------------
// Block: 256 threads = 16(ty) x 16(tx). One block = 128 queries of one (b,h).
// Per thread: 8 q-rows (ty*8+i), 4 k-cols / 4 d-cols (tx*4+j).
// smem (dynamic, 96KB): Qt[64][128] (d-major), Kt[64][64] (d-major),
//                       Vs[64][64] (k-major), Ps[128][64].
__global__ void __launch_bounds__(256, 2) fattn_kernel(
    const float* __restrict__ Q, const float* __restrict__ K,
    const float* __restrict__ V, float* __restrict__ O)
{
    extern __shared__ float sm[];
    float* Qt = sm;                       // [64][128]
    float* Kt = Qt + 64 * ABM;            // [64][64]
    float* Vs = Kt + 64 * ABN;            // [64][64]
    float* Ps = Vs + ABN * 64;            // [128][64]

    int tid = threadIdx.x;
    int tx = tid & 15;
    int ty = tid >> 4;
    int h = blockIdx.y, b = blockIdx.z;
    int q0 = blockIdx.x * ABM;

    const float* Qb = Q + ((size_t)b * S_LEN) * DM + h * DKH;
    const float* Kb = K + ((size_t)b * S_LEN) * DM + h * DKH;
    const float* Vb = V + ((size_t)b * S_LEN) * DM + h * DKH;

    // load Q tile (transposed: Qt[d][q])
    {
        int qi = tid >> 1;
        int d0 = (tid & 1) * 32;
        const float* src = Qb + (size_t)(q0 + qi) * DM + d0;
#pragma unroll
        for (int i = 0; i < 8; i++) {
            float4 v = *(const float4*)(src + 4 * i);
            int d = d0 + 4 * i;
            Qt[(d + 0) * ABM + qi] = v.x;
            Qt[(d + 1) * ABM + qi] = v.y;
            Qt[(d + 2) * ABM + qi] = v.z;
            Qt[(d + 3) * ABM + qi] = v.w;
        }
    }

    float m[8], l[8], Oa[8][4];
#pragma unroll
    for (int i = 0; i < 8; i++) {
        m[i] = -INFINITY; l[i] = 0.f;
#pragma unroll
        for (int j = 0; j < 4; j++) Oa[i][j] = 0.f;
    }

    for (int k0 = 0; k0 < S_LEN; k0 += ABN) {
        // load K tile transposed + V tile direct
        {
            int kj = tid >> 2;
            int d0 = (tid & 3) * 16;
            const float* ksrc = Kb + (size_t)(k0 + kj) * DM + d0;
            const float* vsrc = Vb + (size_t)(k0 + kj) * DM + d0;
#pragma unroll
            for (int i = 0; i < 4; i++) {
                float4 v = *(const float4*)(ksrc + 4 * i);
                int d = d0 + 4 * i;
                Kt[(d + 0) * ABN + kj] = v.x;
                Kt[(d + 1) * ABN + kj] = v.y;
                Kt[(d + 2) * ABN + kj] = v.z;
                Kt[(d + 3) * ABN + kj] = v.w;
                *(float4*)(Vs + kj * 64 + d) = *(const float4*)(vsrc + 4 * i);
            }
        }
        __syncthreads();

        // S = Q K^T   (8q x 4k per thread)
        float s[8][4];
#pragma unroll
        for (int i = 0; i < 8; i++)
#pragma unroll
            for (int j = 0; j < 4; j++) s[i][j] = 0.f;

#pragma unroll 16
        for (int d = 0; d < DKH; d++) {
            float4 qa = *(const float4*)(Qt + d * ABM + ty * 8);
            float4 qb2 = *(const float4*)(Qt + d * ABM + ty * 8 + 4);
            float4 kv = *(const float4*)(Kt + d * ABN + tx * 4);
            float qr[8] = {qa.x, qa.y, qa.z, qa.w, qb2.x, qb2.y, qb2.z, qb2.w};
#pragma unroll
            for (int i = 0; i < 8; i++) {
                s[i][0] += qr[i] * kv.x;
                s[i][1] += qr[i] * kv.y;
                s[i][2] += qr[i] * kv.z;
                s[i][3] += qr[i] * kv.w;
            }
        }

        // online softmax (reduction across the 16 tx threads; same-warp)
#pragma unroll
        for (int i = 0; i < 8; i++) {
            float tm = fmaxf(fmaxf(s[i][0], s[i][1]), fmaxf(s[i][2], s[i][3]));
#pragma unroll
            for (int o = 1; o < 16; o <<= 1)
                tm = fmaxf(tm, __shfl_xor_sync(0xffffffffu, tm, o));
            float mn = fmaxf(m[i], tm);
            float corr = __expf(m[i] - mn);
            m[i] = mn;
            float rs = 0.f;
#pragma unroll
            for (int j = 0; j < 4; j++) {
                s[i][j] = __expf(s[i][j] - mn);
                rs += s[i][j];
            }
#pragma unroll
            for (int o = 1; o < 16; o <<= 1)
                rs += __shfl_xor_sync(0xffffffffu, rs, o);
            l[i] = l[i] * corr + rs;
#pragma unroll
            for (int j = 0; j < 4; j++) Oa[i][j] *= corr;
        }

        // stage P (previous PV reads finished at loop-end sync)
#pragma unroll
        for (int i = 0; i < 8; i++)
            *(float4*)(Ps + (ty * 8 + i) * ABN + tx * 4) =
                make_float4(s[i][0], s[i][1], s[i][2], s[i][3]);
        __syncthreads();

        // O += P V
#pragma unroll 8
        for (int kk = 0; kk < ABN; kk++) {
            float4 vv = *(const float4*)(Vs + kk * 64 + tx * 4);
#pragma unroll
            for (int i = 0; i < 8; i++) {
                float p = Ps[(ty * 8 + i) * ABN + kk];
                Oa[i][0] += p * vv.x;
                Oa[i][1] += p * vv.y;
                Oa[i][2] += p * vv.z;
                Oa[i][3] += p * vv.w;
            }
        }
        __syncthreads();
    }

    // epilogue
#pragma unroll
    for (int i = 0; i < 8; i++) {
        float inv = 1.0f / l[i];
        int row = q0 + ty * 8 + i;
        float4 o;
        o.x = Oa[i][0] * inv;
        o.y = Oa[i][1] * inv;
        o.z = Oa[i][2] * inv;
        o.w = Oa[i][3] * inv;
        *(float4*)(O + ((size_t)(b * S_LEN + row)) * DM + h * DKH + tx * 4) = o;
    }
}

// ---------------- launch ----------------
extern "C" void kernel_launch(void* const* d_in, const int* in_sizes, int n_in,
                              void* d_out, int out_size)
{
    const float* x    = (const float*)d_in[0];
    const float* Wq   = (const float*)d_in[1];
    const float* bq   = (const float*)d_in[2];
    const float* Wk   = (const float*)d_in[3];
    const float* bk   = (const float*)d_in[4];
    const float* Wv   = (const float*)d_in[5];
    const float* bv   = (const float*)d_in[6];
    const float* Wo   = (const float*)d_in[7];
    const float* bo   = (const float*)d_in[8];
    const float* W1   = (const float*)d_in[9];
    const float* b1   = (const float*)d_in[10];
    const float* W2   = (const float*)d_in[11];
    const float* b2   = (const float*)d_in[12];
    const float* ln1a = (const float*)d_in[13];
    const float* ln1b = (const float*)d_in[14];
    const float* ln2a = (const float*)d_in[15];
    const float* ln2b = (const float*)d_in[16];
    float* out = (float*)d_out;

    float *p_n1, *p_q, *p_k, *p_v, *p_ao, *p_h, *p_n2, *p_f1;
    cudaGetSymbolAddress((void**)&p_n1, g_n1);
    cudaGetSymbolAddress((void**)&p_q,  g_q);
    cudaGetSymbolAddress((void**)&p_k,  g_k);
    cudaGetSymbolAddress((void**)&p_v,  g_v);
    cudaGetSymbolAddress((void**)&p_ao, g_ao);
    cudaGetSymbolAddress((void**)&p_h,  g_h);
    cudaGetSymbolAddress((void**)&p_n2, g_n2);
    cudaGetSymbolAddress((void**)&p_f1, g_f1);

    static int attn_smem_set = 0;
    const int ATTN_SMEM = (64 * ABM + 64 * ABN + ABN * 64 + ABM * ABN) * 4; // 96KB
    if (!attn_smem_set) {
        cudaFuncSetAttribute(fattn_kernel,
                             cudaFuncAttributeMaxDynamicSharedMemorySize,
                             ATTN_SMEM);
        attn_smem_set = 1;
    }

    // 1) LN1
    ln_kernel<<<NTOK, 256>>>(x, ln1a, ln1b, p_n1);

    // 2) Q/K/V projections
    dim3 gP(DM / 128, NTOK / 128);
    gemm_kernel<false, false><<<gP, 256>>>(p_n1, Wq, bq, nullptr, p_q, NTOK, DM, DM);
    gemm_kernel<false, false><<<gP, 256>>>(p_n1, Wk, bk, nullptr, p_k, NTOK, DM, DM);
    gemm_kernel<false, false><<<gP, 256>>>(p_n1, Wv, bv, nullptr, p_v, NTOK, DM, DM);

    // 3) flash attention (no 1/sqrt(dk) scaling, per reference)
    fattn_kernel<<<dim3(S_LEN / ABM, NHEAD, BATCH), 256, ATTN_SMEM>>>(
        p_q, p_k, p_v, p_ao);

    // 4) output projection + residual(x)
    gemm_kernel<false, true><<<gP, 256>>>(p_ao, Wo, bo, x, p_h, NTOK, DM, DM);

    // 5) LN2
    ln_kernel<<<NTOK, 256>>>(p_h, ln2a, ln2b, p_n2);

    // 6) FFN up + ReLU
    gemm_kernel<true, false><<<dim3(DFF / 128, NTOK / 128), 256>>>(
        p_n2, W1, b1, nullptr, p_f1, NTOK, DFF, DM);

    // 7) FFN down + residual(h) -> out
    gemm_kernel<false, true><<<dim3(DM / 128, NTOK / 128), 256>>>(
        p_f1, W2, b2, p_h, out, NTOK, DM, DFF);
}

// round 4
// speedup vs baseline: 4.8049x; 1.3842x over previous
#include <cuda_runtime.h>
#include <cuda_bf16.h>
#include <math.h>
#include <cstdint>

#define S_LEN 2048
#define BATCH 2
#define DM    1024
#define NHEAD 16
#define DKH   64
#define DFF   4096
#define NTOK  (BATCH * S_LEN)   // 4096
#define LN_EPS 1e-6f

// flash-attn tiling
#define ABM 128
#define ABN 64

// tc-gemm tiling
#define GBM 128
#define GBN 128
#define GBK 64

#define SW128(o) ((o) ^ (((o) >> 3) & 0x70))

__device__ __forceinline__ uint32_t smem_u32(const void* p) {
    uint32_t a;
    asm("{ .reg .u64 t; cvta.to.shared.u64 t, %1; cvt.u32.u64 %0, t; }"
        : "=r"(a) : "l"(p));
    return a;
}
__device__ __forceinline__ void ldsm_x4(uint32_t addr, uint32_t& r0, uint32_t& r1,
                                        uint32_t& r2, uint32_t& r3) {
    asm volatile("ldmatrix.sync.aligned.m8n8.x4.shared.b16 {%0,%1,%2,%3}, [%4];"
                 : "=r"(r0), "=r"(r1), "=r"(r2), "=r"(r3) : "r"(addr));
}
__device__ __forceinline__ void mma_bf16(float* c, uint32_t a0, uint32_t a1,
                                         uint32_t a2, uint32_t a3,
                                         uint32_t b0, uint32_t b1) {
    asm volatile(
        "mma.sync.aligned.m16n8k16.row.col.f32.bf16.bf16.f32 "
        "{%0,%1,%2,%3}, {%4,%5,%6,%7}, {%8,%9}, {%0,%1,%2,%3};"
        : "+f"(c[0]), "+f"(c[1]), "+f"(c[2]), "+f"(c[3])
        : "r"(a0), "r"(a1), "r"(a2), "r"(a3), "r"(b0), "r"(b1));
}

// ---------------- scratch (device globals; no allocation) ----------------
__device__ float g_n1[NTOK * DM];
__device__ float g_q [NTOK * DM];
__device__ float g_k [NTOK * DM];
__device__ float g_v [NTOK * DM];
__device__ float g_ao[NTOK * DM];
__device__ float g_h [NTOK * DM];
__device__ float g_n2[NTOK * DM];
__device__ float g_f1[NTOK * DFF];

// ---------------- LayerNorm (unbiased variance, scalar alpha/beta) -------
__global__ void __launch_bounds__(256) ln_kernel(
    const float* __restrict__ x, const float* __restrict__ alpha,
    const float* __restrict__ beta, float* __restrict__ y)
{
    int row = blockIdx.x;
    int tid = threadIdx.x;
    const float4* x4 = (const float4*)(x + (size_t)row * DM);
    float4 v = x4[tid];
    float s = v.x + v.y + v.z + v.w;
    float q = v.x * v.x + v.y * v.y + v.z * v.z + v.w * v.w;

    __shared__ float rs[8], rq[8];
#pragma unroll
    for (int o = 16; o; o >>= 1) {
        s += __shfl_xor_sync(0xffffffffu, s, o);
        q += __shfl_xor_sync(0xffffffffu, q, o);
    }
    if ((tid & 31) == 0) { rs[tid >> 5] = s; rq[tid >> 5] = q; }
    __syncthreads();
    s = 0.f; q = 0.f;
#pragma unroll
    for (int i = 0; i < 8; i++) { s += rs[i]; q += rq[i]; }

    float mean = s * (1.0f / DM);
    float var  = (q - (float)DM * mean * mean) * (1.0f / (DM - 1));
    float a    = alpha[0];
    float b    = beta[0];
    float inv  = a / (sqrtf(var) + LN_EPS);

    float4 o;
    o.x = (v.x - mean) * inv + b;
    o.y = (v.y - mean) * inv + b;
    o.z = (v.z - mean) * inv + b;
    o.w = (v.w - mean) * inv + b;
    ((float4*)(y + (size_t)row * DM))[tid] = o;
}

// ---------------- HMMA GEMM: C = A[M,K] @ B[K,N] + bias (+res)(+relu) ----
// Split-bf16 3-term fp32 emulation: A=Ah+Al, B=Bh+Bl (bf16),
// D += Ah*Bh + Ah*Bl + Al*Bh.
// 128x128 tile, BK=64, 256 threads (8 warps, 2x4), 64x32 per warp.
template<bool RELU, bool RES>
__global__ void __launch_bounds__(256, 2) tc_gemm_kernel(
    const float* __restrict__ A, const float* __restrict__ B,
    const float* __restrict__ bias, const float* __restrict__ res,
    float* __restrict__ C, int M, int N, int K)
{
    extern __shared__ char sm[];
    char* Ah = sm;                 // [128][64] bf16, SW128 rows (16KB)
    char* Al = sm + 16384;
    char* Bh = sm + 32768;         // [n:128][k:64] bf16, SW128
    char* Bl = sm + 49152;

    const int tid = threadIdx.x;
    const int wid = tid >> 5;
    const int lid = tid & 31;
    const int nb = blockIdx.x, mb = blockIdx.y;

    const int warp_m = (wid >> 2) * 64;    // 0 or 64
    const int warp_n = (wid & 3) * 32;     // 0,32,64,96

    const uint32_t ah_u = smem_u32(Ah);
    const uint32_t al_u = smem_u32(Al);
    const uint32_t bh_u = smem_u32(Bh);
    const uint32_t bl_u = smem_u32(Bl);

    // ldmatrix lane addressing (SW128: XOR mask fixed per lane)
    const int a_row = warp_m + (lid & 15);
    const uint32_t a_cb = (uint32_t)((lid >> 4) * 16);
    const int b_row_off = ((lid & 16) >> 1) + (lid & 7);
    const uint32_t b_cb = (lid & 8) ? 16u : 0u;
    const uint32_t xm = (uint32_t)((lid & 7) << 4);

    float acc[4][4][4];
#pragma unroll
    for (int i = 0; i < 4; i++)
#pragma unroll
        for (int j = 0; j < 4; j++)
#pragma unroll
            for (int r = 0; r < 4; r++) acc[i][j][r] = 0.f;

    // staging assignments
    const int ar = tid >> 1;
    const int akh = (tid & 1) * 32;
    const float* aSrc = A + (size_t)(mb * GBM + ar) * K + akh;
    const int kp = tid >> 3;
    const int nq = tid & 7;
    const float* bSrc = B + (size_t)(2 * kp) * N + nb * GBN + nq * 4;

    const int niter = K / GBK;
    for (int kt = 0; kt < niter; kt++) {
        // ---- stage A (fp32 -> hi/lo bf16, SW128) ----
        const float* as = aSrc + kt * GBK;
#pragma unroll
        for (int i = 0; i < 8; i++) {
            float4 v = *(const float4*)(as + 4 * i);
            __nv_bfloat162 h0 = __floats2bfloat162_rn(v.x, v.y);
            __nv_bfloat162 h1 = __floats2bfloat162_rn(v.z, v.w);
            float2 f0 = __bfloat1622float2(h0), f1 = __bfloat1622float2(h1);
            __nv_bfloat162 l0 = __floats2bfloat162_rn(v.x - f0.x, v.y - f0.y);
            __nv_bfloat162 l1 = __floats2bfloat162_rn(v.z - f1.x, v.w - f1.y);
            uint32_t base = ar * 128 + (akh + 4 * i) * 2;
            uint32_t o0 = SW128(base);
            uint32_t o1 = SW128(base + 4);
            *(__nv_bfloat162*)(Ah + o0) = h0;
            *(__nv_bfloat162*)(Ah + o1) = h1;
            *(__nv_bfloat162*)(Al + o0) = l0;
            *(__nv_bfloat162*)(Al + o1) = l1;
        }
        // ---- stage B transposed ([n][k], hi/lo) ----
        const float* bs = bSrc + (size_t)kt * GBK * N;
#pragma unroll
        for (int i = 0; i < 4; i++) {
            float4 u0 = *(const float4*)(bs + i * 32);
            float4 u1 = *(const float4*)(bs + i * 32 + N);
            float pa[4] = {u0.x, u0.y, u0.z, u0.w};
            float pb[4] = {u1.x, u1.y, u1.z, u1.w};
#pragma unroll
            for (int c = 0; c < 4; c++) {
                int n = nq * 4 + i * 32 + c;
                __nv_bfloat162 h = __floats2bfloat162_rn(pa[c], pb[c]);
                float2 hf = __bfloat1622float2(h);
                __nv_bfloat162 l = __floats2bfloat162_rn(pa[c] - hf.x, pb[c] - hf.y);
                uint32_t o = SW128((uint32_t)(n * 128 + kp * 4));
                *(__nv_bfloat162*)(Bh + o) = h;
                *(__nv_bfloat162*)(Bl + o) = l;
            }
        }
        __syncthreads();

        // ---- MMA: 4 k16 steps ----
#pragma unroll
        for (int s = 0; s < 4; s++) {
            uint32_t bh[8], bl[8];
#pragma unroll
            for (int pr = 0; pr < 2; pr++) {
                uint32_t roff = (uint32_t)(warp_n + pr * 16 + b_row_off) * 128;
                uint32_t coff = (uint32_t)(s * 32 + b_cb) ^ xm;
                ldsm_x4(bh_u + roff + coff, bh[pr*4+0], bh[pr*4+1], bh[pr*4+2], bh[pr*4+3]);
                ldsm_x4(bl_u + roff + coff, bl[pr*4+0], bl[pr*4+1], bl[pr*4+2], bl[pr*4+3]);
            }
#pragma unroll
            for (int mt = 0; mt < 4; mt++) {
                uint32_t roff = (uint32_t)(a_row + mt * 16) * 128;
                uint32_t coff = (uint32_t)(s * 32 + a_cb) ^ xm;
                uint32_t ah0, ah1, ah2, ah3, al0, al1, al2, al3;
                ldsm_x4(ah_u + roff + coff, ah0, ah1, ah2, ah3);
                ldsm_x4(al_u + roff + coff, al0, al1, al2, al3);
#pragma unroll
                for (int nt = 0; nt < 4; nt++) {
                    uint32_t hb0 = bh[(nt >> 1) * 4 + (nt & 1) * 2];
                    uint32_t hb1 = bh[(nt >> 1) * 4 + (nt & 1) * 2 + 1];
                    uint32_t lb0 = bl[(nt >> 1) * 4 + (nt & 1) * 2];
                    uint32_t lb1 = bl[(nt >> 1) * 4 + (nt & 1) * 2 + 1];
                    mma_bf16(acc[mt][nt], ah0, ah1, ah2, ah3, hb0, hb1);
                    mma_bf16(acc[mt][nt], ah0, ah1, ah2, ah3, lb0, lb1);
                    mma_bf16(acc[mt][nt], al0, al1, al2, al3, hb0, hb1);
                }
            }
        }
        __syncthreads();
    }

    // ---- epilogue: direct from fragments ----
    {
        int g = lid >> 2, tig = lid & 3;
        int base_row = mb * GBM + warp_m + g;
        int base_col = nb * GBN + warp_n + tig * 2;
#pragma unroll
        for (int mt = 0; mt < 4; mt++) {
#pragma unroll
            for (int nt = 0; nt < 4; nt++) {
                int col = base_col + nt * 8;
                float2 bb = *(const float2*)(bias + col);
#pragma unroll
                for (int hrow = 0; hrow < 2; hrow++) {
                    int row = base_row + mt * 16 + hrow * 8;
                    float2 o;
                    o.x = acc[mt][nt][hrow * 2 + 0] + bb.x;
                    o.y = acc[mt][nt][hrow * 2 + 1] + bb.y;
                    if (RES) {
                        float2 r2 = *(const float2*)(res + (size_t)row * N + col);
                        o.x += r2.x; o.y += r2.y;
                    }
                    if (RELU) {
                        o.x = fmaxf(o.x, 0.f);
                        o.y = fmaxf(o.y, 0.f);
                    }
                    *(float2*)(C + (size_t)row * N + col) = o;
                }
            }
        }
    }
}

// ---------------- Flash attention (fp32 SIMT, online softmax) ------------
__global__ void __launch_bounds__(256, 2) fattn_kernel(
    const float* __restrict__ Q, const float* __restrict__ K,
    const float* __restrict__ V, float* __restrict__ O)
{
    extern __shared__ float smf[];
    float* Qt = smf;                      // [64][128]
    float* Kt = Qt + 64 * ABM;            // [64][64]
    float* Vs = Kt + 64 * ABN;            // [64][64]
    float* Ps = Vs + ABN * 64;            // [128][64]

    int tid = threadIdx.x;
    int tx = tid & 15;
    int ty = tid >> 4;
    int h = blockIdx.y, b = blockIdx.z;
    int q0 = blockIdx.x * ABM;

    const float* Qb = Q + ((size_t)b * S_LEN) * DM + h * DKH;
    const float* Kb = K + ((size_t)b * S_LEN) * DM + h * DKH;
    const float* Vb = V + ((size_t)b * S_LEN) * DM + h * DKH;

    {
        int qi = tid >> 1;
        int d0 = (tid & 1) * 32;
        const float* src = Qb + (size_t)(q0 + qi) * DM + d0;
#pragma unroll
        for (int i = 0; i < 8; i++) {
            float4 v = *(const float4*)(src + 4 * i);
            int d = d0 + 4 * i;
            Qt[(d + 0) * ABM + qi] = v.x;
            Qt[(d + 1) * ABM + qi] = v.y;
            Qt[(d + 2) * ABM + qi] = v.z;
            Qt[(d + 3) * ABM + qi] = v.w;
        }
    }

    float m[8], l[8], Oa[8][4];
#pragma unroll
    for (int i = 0; i < 8; i++) {
        m[i] = -INFINITY; l[i] = 0.f;
#pragma unroll
        for (int j = 0; j < 4; j++) Oa[i][j] = 0.f;
    }

    for (int k0 = 0; k0 < S_LEN; k0 += ABN) {
        {
            int kj = tid >> 2;
            int d0 = (tid & 3) * 16;
            const float* ksrc = Kb + (size_t)(k0 + kj) * DM + d0;
            const float* vsrc = Vb + (size_t)(k0 + kj) * DM + d0;
#pragma unroll
            for (int i = 0; i < 4; i++) {
                float4 v = *(const float4*)(ksrc + 4 * i);
                int d = d0 + 4 * i;
                Kt[(d + 0) * ABN + kj] = v.x;
                Kt[(d + 1) * ABN + kj] = v.y;
                Kt[(d + 2) * ABN + kj] = v.z;
                Kt[(d + 3) * ABN + kj] = v.w;
                *(float4*)(Vs + kj * 64 + d) = *(const float4*)(vsrc + 4 * i);
            }
        }
        __syncthreads();

        float s[8][4];
#pragma unroll
        for (int i = 0; i < 8; i++)
#pragma unroll
            for (int j = 0; j < 4; j++) s[i][j] = 0.f;

#pragma unroll 16
        for (int d = 0; d < DKH; d++) {
            float4 qa = *(const float4*)(Qt + d * ABM + ty * 8);
            float4 qb2 = *(const float4*)(Qt + d * ABM + ty * 8 + 4);
            float4 kv = *(const float4*)(Kt + d * ABN + tx * 4);
            float qr[8] = {qa.x, qa.y, qa.z, qa.w, qb2.x, qb2.y, qb2.z, qb2.w};
#pragma unroll
            for (int i = 0; i < 8; i++) {
                s[i][0] += qr[i] * kv.x;
                s[i][1] += qr[i] * kv.y;
                s[i][2] += qr[i] * kv.z;
                s[i][3] += qr[i] * kv.w;
            }
        }

#pragma unroll
        for (int i = 0; i < 8; i++) {
            float tm = fmaxf(fmaxf(s[i][0], s[i][1]), fmaxf(s[i][2], s[i][3]));
#pragma unroll
            for (int o = 1; o < 16; o <<= 1)
                tm = fmaxf(tm, __shfl_xor_sync(0xffffffffu, tm, o));
            float mn = fmaxf(m[i], tm);
            float corr = __expf(m[i] - mn);
            m[i] = mn;
            float rsum = 0.f;
#pragma unroll
            for (int j = 0; j < 4; j++) {
                s[i][j] = __expf(s[i][j] - mn);
                rsum += s[i][j];
            }
#pragma unroll
            for (int o = 1; o < 16; o <<= 1)
                rsum += __shfl_xor_sync(0xffffffffu, rsum, o);
            l[i] = l[i] * corr + rsum;
#pragma unroll
            for (int j = 0; j < 4; j++) Oa[i][j] *= corr;
        }

#pragma unroll
        for (int i = 0; i < 8; i++)
            *(float4*)(Ps + (ty * 8 + i) * ABN + tx * 4) =
                make_float4(s[i][0], s[i][1], s[i][2], s[i][3]);
        __syncthreads();

#pragma unroll 8
        for (int kk = 0; kk < ABN; kk++) {
            float4 vv = *(const float4*)(Vs + kk * 64 + tx * 4);
#pragma unroll
            for (int i = 0; i < 8; i++) {
                float p = Ps[(ty * 8 + i) * ABN + kk];
                Oa[i][0] += p * vv.x;
                Oa[i][1] += p * vv.y;
                Oa[i][2] += p * vv.z;
                Oa[i][3] += p * vv.w;
            }
        }
        __syncthreads();
    }

#pragma unroll
    for (int i = 0; i < 8; i++) {
        float inv = 1.0f / l[i];
        int row = q0 + ty * 8 + i;
        float4 o;
        o.x = Oa[i][0] * inv;
        o.y = Oa[i][1] * inv;
        o.z = Oa[i][2] * inv;
        o.w = Oa[i][3] * inv;
        *(float4*)(O + ((size_t)(b * S_LEN + row)) * DM + h * DKH + tx * 4) = o;
    }
}

// ---------------- launch ----------------
extern "C" void kernel_launch(void* const* d_in, const int* in_sizes, int n_in,
                              void* d_out, int out_size)
{
    const float* x    = (const float*)d_in[0];
    const float* Wq   = (const float*)d_in[1];
    const float* bq   = (const float*)d_in[2];
    const float* Wk   = (const float*)d_in[3];
    const float* bk   = (const float*)d_in[4];
    const float* Wv   = (const float*)d_in[5];
    const float* bv   = (const float*)d_in[6];
    const float* Wo   = (const float*)d_in[7];
    const float* bo   = (const float*)d_in[8];
    const float* W1   = (const float*)d_in[9];
    const float* b1   = (const float*)d_in[10];
    const float* W2   = (const float*)d_in[11];
    const float* b2   = (const float*)d_in[12];
    const float* ln1a = (const float*)d_in[13];
    const float* ln1b = (const float*)d_in[14];
    const float* ln2a = (const float*)d_in[15];
    const float* ln2b = (const float*)d_in[16];
    float* out = (float*)d_out;

    float *p_n1, *p_q, *p_k, *p_v, *p_ao, *p_h, *p_n2, *p_f1;
    cudaGetSymbolAddress((void**)&p_n1, g_n1);
    cudaGetSymbolAddress((void**)&p_q,  g_q);
    cudaGetSymbolAddress((void**)&p_k,  g_k);
    cudaGetSymbolAddress((void**)&p_v,  g_v);
    cudaGetSymbolAddress((void**)&p_ao, g_ao);
    cudaGetSymbolAddress((void**)&p_h,  g_h);
    cudaGetSymbolAddress((void**)&p_n2, g_n2);
    cudaGetSymbolAddress((void**)&p_f1, g_f1);

    const int GEMM_SMEM = 65536;   // 4 x 16KB bf16 tiles
    const int ATTN_SMEM = (64 * ABM + 64 * ABN + ABN * 64 + ABM * ABN) * 4;

    cudaFuncSetAttribute(fattn_kernel,
                         cudaFuncAttributeMaxDynamicSharedMemorySize, ATTN_SMEM);
    cudaFuncSetAttribute(tc_gemm_kernel<false, false>,
                         cudaFuncAttributeMaxDynamicSharedMemorySize, GEMM_SMEM);
    cudaFuncSetAttribute(tc_gemm_kernel<false, true>,
                         cudaFuncAttributeMaxDynamicSharedMemorySize, GEMM_SMEM);
    cudaFuncSetAttribute(tc_gemm_kernel<true, false>,
                         cudaFuncAttributeMaxDynamicSharedMemorySize, GEMM_SMEM);

    // 1) LN1
    ln_kernel<<<NTOK, 256>>>(x, ln1a, ln1b, p_n1);

    // 2) Q/K/V projections (HMMA bf16 split)
    dim3 gP(DM / GBN, NTOK / GBM);   // (8, 32)
    tc_gemm_kernel<false, false><<<gP, 256, GEMM_SMEM>>>(p_n1, Wq, bq, nullptr, p_q, NTOK, DM, DM);
    tc_gemm_kernel<false, false><<<gP, 256, GEMM_SMEM>>>(p_n1, Wk, bk, nullptr, p_k, NTOK, DM, DM);
    tc_gemm_kernel<false, false><<<gP, 256, GEMM_SMEM>>>(p_n1, Wv, bv, nullptr, p_v, NTOK, DM, DM);

    // 3) flash attention (no 1/sqrt(dk) scaling, per reference)
    fattn_kernel<<<dim3(S_LEN / ABM, NHEAD, BATCH), 256, ATTN_SMEM>>>(
        p_q, p_k, p_v, p_ao);

    // 4) output projection + residual(x)
    tc_gemm_kernel<false, true><<<gP, 256, GEMM_SMEM>>>(p_ao, Wo, bo, x, p_h, NTOK, DM, DM);

    // 5) LN2
    ln_kernel<<<NTOK, 256>>>(p_h, ln2a, ln2b, p_n2);

    // 6) FFN up + ReLU
    tc_gemm_kernel<true, false><<<dim3(DFF / GBN, NTOK / GBM), 256, GEMM_SMEM>>>(
        p_n2, W1, b1, nullptr, p_f1, NTOK, DFF, DM);

    // 7) FFN down + residual(h) -> out
    tc_gemm_kernel<false, true><<<dim3(DM / GBN, NTOK / GBM), 256, GEMM_SMEM>>>(
        p_f1, W2, b2, p_h, out, NTOK, DM, DFF);
}

// round 5
// speedup vs baseline: 7.2003x; 1.4985x over previous
#include <cuda_runtime.h>
#include <cuda_fp16.h>
#include <math.h>
#include <cstdint>

#define S_LEN 2048
#define BATCH 2
#define DM    1024
#define NHEAD 16
#define DKH   64
#define DFF   4096
#define NTOK  (BATCH * S_LEN)   // 4096
#define LN_EPS 1e-6f

#define ABM 128
#define ABN 64

#define GBM 128
#define GBN 128
#define GBK 64

__device__ __forceinline__ uint32_t smem_u32(const void* p) {
    uint32_t a;
    asm("{ .reg .u64 t; cvta.to.shared.u64 t, %1; cvt.u32.u64 %0, t; }"
        : "=r"(a) : "l"(p));
    return a;
}
__device__ __forceinline__ void ldsm_x4(uint32_t addr, uint32_t& r0, uint32_t& r1,
                                        uint32_t& r2, uint32_t& r3) {
    asm volatile("ldmatrix.sync.aligned.m8n8.x4.shared.b16 {%0,%1,%2,%3}, [%4];"
                 : "=r"(r0), "=r"(r1), "=r"(r2), "=r"(r3) : "r"(addr));
}
__device__ __forceinline__ void mma_f16(float* c, uint32_t a0, uint32_t a1,
                                        uint32_t a2, uint32_t a3,
                                        uint32_t b0, uint32_t b1) {
    asm volatile(
        "mma.sync.aligned.m16n8k16.row.col.f32.f16.f16.f32 "
        "{%0,%1,%2,%3}, {%4,%5,%6,%7}, {%8,%9}, {%0,%1,%2,%3};"
        : "+f"(c[0]), "+f"(c[1]), "+f"(c[2]), "+f"(c[3])
        : "r"(a0), "r"(a1), "r"(a2), "r"(a3), "r"(b0), "r"(b1));
}
#define CP_ASYNC16(dst, src) \
    asm volatile("cp.async.cg.shared.global [%0], [%1], 16;" :: "r"(dst), "l"(src))
#define CP_COMMIT() asm volatile("cp.async.commit_group;" ::: "memory")
#define CP_WAIT0()  asm volatile("cp.async.wait_group 0;" ::: "memory")

// ---------------- scratch (device globals; no allocation) ----------------
__device__ __half g_n1h[NTOK * DM];
__device__ __half g_n1l[NTOK * DM];
__device__ float  g_q [NTOK * DM];
__device__ float  g_k [NTOK * DM];
__device__ float  g_v [NTOK * DM];
__device__ __half g_aoh[NTOK * DM];
__device__ float  g_h [NTOK * DM];
__device__ __half g_n2h[NTOK * DM];
__device__ __half g_n2l[NTOK * DM];
__device__ __half g_f1h[NTOK * DFF];
// transposed split weights [N][K]
__device__ __half g_wqh[DM * DM],  g_wql[DM * DM];
__device__ __half g_wkh[DM * DM],  g_wkl[DM * DM];
__device__ __half g_wvh[DM * DM],  g_wvl[DM * DM];
__device__ __half g_woh[DM * DM],  g_wol[DM * DM];
__device__ __half g_w1h[DM * DFF], g_w1l[DM * DFF];
__device__ __half g_w2h[DFF * DM], g_w2l[DFF * DM];

// ---------------- weight transpose + fp16 hi/lo split ---------------------
// W[K][N] fp32 -> Bh[N][K], Bl[N][K] fp16
__global__ void __launch_bounds__(256) wsplit_kernel(
    const float* __restrict__ W, __half* __restrict__ Bh, __half* __restrict__ Bl,
    int K, int N)
{
    __shared__ float tile[32][33];
    int n0 = blockIdx.x * 32, k0 = blockIdx.y * 32;
    int tx = threadIdx.x & 31, ty = threadIdx.x >> 5;
#pragma unroll
    for (int i = 0; i < 4; i++)
        tile[ty + 8 * i][tx] = W[(size_t)(k0 + ty + 8 * i) * N + n0 + tx];
    __syncthreads();
#pragma unroll
    for (int i = 0; i < 4; i++) {
        int nl = ty + 8 * i;
        float w = tile[tx][nl];
        __half h = __float2half_rn(w);
        __half l = __float2half_rn(w - __half2float(h));
        size_t o = (size_t)(n0 + nl) * K + k0 + tx;
        Bh[o] = h;
        Bl[o] = l;
    }
}

// ---------------- LayerNorm -> fp16 hi/lo ---------------------------------
__global__ void __launch_bounds__(256) ln_kernel(
    const float* __restrict__ x, const float* __restrict__ alpha,
    const float* __restrict__ beta, __half* __restrict__ yh,
    __half* __restrict__ yl)
{
    int row = blockIdx.x;
    int tid = threadIdx.x;
    const float4* x4 = (const float4*)(x + (size_t)row * DM);
    float4 v = x4[tid];
    float s = v.x + v.y + v.z + v.w;
    float q = v.x * v.x + v.y * v.y + v.z * v.z + v.w * v.w;

    __shared__ float rs[8], rq[8];
#pragma unroll
    for (int o = 16; o; o >>= 1) {
        s += __shfl_xor_sync(0xffffffffu, s, o);
        q += __shfl_xor_sync(0xffffffffu, q, o);
    }
    if ((tid & 31) == 0) { rs[tid >> 5] = s; rq[tid >> 5] = q; }
    __syncthreads();
    s = 0.f; q = 0.f;
#pragma unroll
    for (int i = 0; i < 8; i++) { s += rs[i]; q += rq[i]; }

    float mean = s * (1.0f / DM);
    float var  = (q - (float)DM * mean * mean) * (1.0f / (DM - 1));
    float a    = alpha[0];
    float b    = beta[0];
    float inv  = a / (sqrtf(var) + LN_EPS);

    float o0 = (v.x - mean) * inv + b;
    float o1 = (v.y - mean) * inv + b;
    float o2 = (v.z - mean) * inv + b;
    float o3 = (v.w - mean) * inv + b;

    __half2 h0 = __floats2half2_rn(o0, o1);
    __half2 h1 = __floats2half2_rn(o2, o3);
    float2 hf0 = __half22float2(h0), hf1 = __half22float2(h1);
    __half2 l0 = __floats2half2_rn(o0 - hf0.x, o1 - hf0.y);
    __half2 l1 = __floats2half2_rn(o2 - hf1.x, o3 - hf1.y);

    uint2 uh, ul;
    uh.x = *(uint32_t*)&h0; uh.y = *(uint32_t*)&h1;
    ul.x = *(uint32_t*)&l0; ul.y = *(uint32_t*)&l1;
    *(uint2*)(yh + (size_t)row * DM + tid * 4) = uh;
    *(uint2*)(yl + (size_t)row * DM + tid * 4) = ul;
}

// ---------------- HMMA GEMM (preconverted fp16, cp.async pipeline) --------
// C = A[M,K] @ B^T (B stored [N][K]) + bias (+res)(+relu)
// TERMS=2: A single, B hi/lo   |  TERMS=3: A hi/lo, B hi/lo (3 products)
// 128x128 tile, BK=64, 2-stage cp.async double buffer, 8 warps (2x4).
template<int TERMS, bool RELU, bool RES, bool HOUT>
__global__ void __launch_bounds__(256) tc2_gemm(
    const __half* __restrict__ Ah, const __half* __restrict__ Al,
    const __half* __restrict__ Bh, const __half* __restrict__ Bl,
    const float* __restrict__ bias, const float* __restrict__ res,
    float* __restrict__ Cf, __half* __restrict__ Ch, int M, int N, int K)
{
    extern __shared__ char sm[];
    constexpr int TILES = (TERMS == 3) ? 4 : 3;
    constexpr uint32_t AH_OFF = 0;
    constexpr uint32_t AL_OFF = 16384;                       // 3-term only
    constexpr uint32_t BH_OFF = (TERMS == 3) ? 32768u : 16384u;
    constexpr uint32_t BL_OFF = BH_OFF + 16384u;
    const uint32_t STAGE = TILES * 16384u;

    const int tid = threadIdx.x;
    const int wid = tid >> 5;
    const int lid = tid & 31;
    const int nb = blockIdx.x, mb = blockIdx.y;

    const int warp_m = (wid >> 2) * 64;
    const int warp_n = (wid & 3) * 32;

    const uint32_t smb = smem_u32(sm);

    // ldmatrix lane addressing (SW128 row-xor, validated in R4)
    const int a_row = warp_m + (lid & 15);
    const uint32_t a_cb = (uint32_t)((lid >> 4) * 16);
    const int b_row_off = ((lid & 16) >> 1) + (lid & 7);
    const uint32_t b_cb = (lid & 8) ? 16u : 0u;
    const uint32_t xm = (uint32_t)((lid & 7) << 4);

    float acc[4][4][4];
#pragma unroll
    for (int i = 0; i < 4; i++)
#pragma unroll
        for (int j = 0; j < 4; j++)
#pragma unroll
            for (int r = 0; r < 4; r++) acc[i][j][r] = 0.f;

    // staging: thread covers chunk (r, j): j = 16B index in 128B row
    const int sj = tid & 7;
    const int sr0 = tid >> 3;     // +32 per iteration

    const int niter = K / GBK;

    // ---- stage function (as lambda via macro-ish inline) ----
    auto stage = [&](int kt, int buf) {
        uint32_t base = smb + (uint32_t)buf * STAGE;
        const __half* aS = Ah + (size_t)(mb * GBM) * K + kt * GBK + sj * 8;
        const __half* bS = Bh + (size_t)(nb * GBN) * K + kt * GBK + sj * 8;
        const __half* blS = Bl + (size_t)(nb * GBN) * K + kt * GBK + sj * 8;
#pragma unroll
        for (int i = 0; i < 4; i++) {
            int r = i * 32 + sr0;
            uint32_t sw = (uint32_t)(r * 128 + ((sj * 16) ^ ((r & 7) << 4)));
            CP_ASYNC16(base + AH_OFF + sw, aS + (size_t)r * K);
            if (TERMS == 3)
                CP_ASYNC16(base + AL_OFF + sw, Al + (size_t)(mb * GBM + r) * K + kt * GBK + sj * 8);
            CP_ASYNC16(base + BH_OFF + sw, bS + (size_t)r * K);
            CP_ASYNC16(base + BL_OFF + sw, blS + (size_t)r * K);
        }
    };

    stage(0, 0);
    CP_COMMIT();

    for (int kt = 0; kt < niter; kt++) {
        int buf = kt & 1;
        CP_WAIT0();
        __syncthreads();
        if (kt + 1 < niter) {
            stage(kt + 1, buf ^ 1);
            CP_COMMIT();
        }

        uint32_t ah_u = smb + (uint32_t)buf * STAGE + AH_OFF;
        uint32_t al_u = smb + (uint32_t)buf * STAGE + AL_OFF;
        uint32_t bh_u = smb + (uint32_t)buf * STAGE + BH_OFF;
        uint32_t bl_u = smb + (uint32_t)buf * STAGE + BL_OFF;

#pragma unroll
        for (int s = 0; s < 4; s++) {
            uint32_t bhf[8], blf[8];
#pragma unroll
            for (int pr = 0; pr < 2; pr++) {
                uint32_t roff = (uint32_t)(warp_n + pr * 16 + b_row_off) * 128;
                uint32_t coff = (uint32_t)(s * 32 + b_cb) ^ xm;
                ldsm_x4(bh_u + roff + coff, bhf[pr*4+0], bhf[pr*4+1], bhf[pr*4+2], bhf[pr*4+3]);
                ldsm_x4(bl_u + roff + coff, blf[pr*4+0], blf[pr*4+1], blf[pr*4+2], blf[pr*4+3]);
            }
#pragma unroll
            for (int mt = 0; mt < 4; mt++) {
                uint32_t roff = (uint32_t)(a_row + mt * 16) * 128;
                uint32_t coff = (uint32_t)(s * 32 + a_cb) ^ xm;
                uint32_t a0, a1, a2, a3;
                ldsm_x4(ah_u + roff + coff, a0, a1, a2, a3);
                uint32_t l0 = 0, l1 = 0, l2 = 0, l3 = 0;
                if (TERMS == 3) ldsm_x4(al_u + roff + coff, l0, l1, l2, l3);
#pragma unroll
                for (int nt = 0; nt < 4; nt++) {
                    uint32_t hb0 = bhf[(nt >> 1) * 4 + (nt & 1) * 2];
                    uint32_t hb1 = bhf[(nt >> 1) * 4 + (nt & 1) * 2 + 1];
                    uint32_t lb0 = blf[(nt >> 1) * 4 + (nt & 1) * 2];
                    uint32_t lb1 = blf[(nt >> 1) * 4 + (nt & 1) * 2 + 1];
                    mma_f16(acc[mt][nt], a0, a1, a2, a3, hb0, hb1);
                    mma_f16(acc[mt][nt], a0, a1, a2, a3, lb0, lb1);
                    if (TERMS == 3)
                        mma_f16(acc[mt][nt], l0, l1, l2, l3, hb0, hb1);
                }
            }
        }
        __syncthreads();
    }

    // ---- epilogue: direct from fragments ----
    {
        int g = lid >> 2, tig = lid & 3;
        int base_row = mb * GBM + warp_m + g;
        int base_col = nb * GBN + warp_n + tig * 2;
#pragma unroll
        for (int mt = 0; mt < 4; mt++) {
#pragma unroll
            for (int nt = 0; nt < 4; nt++) {
                int col = base_col + nt * 8;
                float2 bb = *(const float2*)(bias + col);
#pragma unroll
                for (int hrow = 0; hrow < 2; hrow++) {
                    int row = base_row + mt * 16 + hrow * 8;
                    float2 o;
                    o.x = acc[mt][nt][hrow * 2 + 0] + bb.x;
                    o.y = acc[mt][nt][hrow * 2 + 1] + bb.y;
                    if (RES) {
                        float2 r2 = *(const float2*)(res + (size_t)row * N + col);
                        o.x += r2.x; o.y += r2.y;
                    }
                    if (RELU) {
                        o.x = fmaxf(o.x, 0.f);
                        o.y = fmaxf(o.y, 0.f);
                    }
                    if (HOUT) {
                        __half2 hv = __floats2half2_rn(o.x, o.y);
                        *(__half2*)(Ch + (size_t)row * N + col) = hv;
                    } else {
                        *(float2*)(Cf + (size_t)row * N + col) = o;
                    }
                }
            }
        }
    }
}

// ---------------- Flash attention (fp32 SIMT, fp16 output) ----------------
__global__ void __launch_bounds__(256, 2) fattn_kernel(
    const float* __restrict__ Q, const float* __restrict__ K,
    const float* __restrict__ V, __half* __restrict__ Oh)
{
    extern __shared__ float smf[];
    float* Qt = smf;                      // [64][128]
    float* Kt = Qt + 64 * ABM;            // [64][64]
    float* Vs = Kt + 64 * ABN;            // [64][64]
    float* Ps = Vs + ABN * 64;            // [128][64]

    int tid = threadIdx.x;
    int tx = tid & 15;
    int ty = tid >> 4;
    int h = blockIdx.y, b = blockIdx.z;
    int q0 = blockIdx.x * ABM;

    const float* Qb = Q + ((size_t)b * S_LEN) * DM + h * DKH;
    const float* Kb = K + ((size_t)b * S_LEN) * DM + h * DKH;
    const float* Vb = V + ((size_t)b * S_LEN) * DM + h * DKH;

    {
        int qi = tid >> 1;
        int d0 = (tid & 1) * 32;
        const float* src = Qb + (size_t)(q0 + qi) * DM + d0;
#pragma unroll
        for (int i = 0; i < 8; i++) {
            float4 v = *(const float4*)(src + 4 * i);
            int d = d0 + 4 * i;
            Qt[(d + 0) * ABM + qi] = v.x;
            Qt[(d + 1) * ABM + qi] = v.y;
            Qt[(d + 2) * ABM + qi] = v.z;
            Qt[(d + 3) * ABM + qi] = v.w;
        }
    }

    float m[8], l[8], Oa[8][4];
#pragma unroll
    for (int i = 0; i < 8; i++) {
        m[i] = -INFINITY; l[i] = 0.f;
#pragma unroll
        for (int j = 0; j < 4; j++) Oa[i][j] = 0.f;
    }

    for (int k0 = 0; k0 < S_LEN; k0 += ABN) {
        {
            int kj = tid >> 2;
            int d0 = (tid & 3) * 16;
            const float* ksrc = Kb + (size_t)(k0 + kj) * DM + d0;
            const float* vsrc = Vb + (size_t)(k0 + kj) * DM + d0;
#pragma unroll
            for (int i = 0; i < 4; i++) {
                float4 v = *(const float4*)(ksrc + 4 * i);
                int d = d0 + 4 * i;
                Kt[(d + 0) * ABN + kj] = v.x;
                Kt[(d + 1) * ABN + kj] = v.y;
                Kt[(d + 2) * ABN + kj] = v.z;
                Kt[(d + 3) * ABN + kj] = v.w;
                *(float4*)(Vs + kj * 64 + d) = *(const float4*)(vsrc + 4 * i);
            }
        }
        __syncthreads();

        float s[8][4];
#pragma unroll
        for (int i = 0; i < 8; i++)
#pragma unroll
            for (int j = 0; j < 4; j++) s[i][j] = 0.f;

#pragma unroll 16
        for (int d = 0; d < DKH; d++) {
            float4 qa = *(const float4*)(Qt + d * ABM + ty * 8);
            float4 qb2 = *(const float4*)(Qt + d * ABM + ty * 8 + 4);
            float4 kv = *(const float4*)(Kt + d * ABN + tx * 4);
            float qr[8] = {qa.x, qa.y, qa.z, qa.w, qb2.x, qb2.y, qb2.z, qb2.w};
#pragma unroll
            for (int i = 0; i < 8; i++) {
                s[i][0] += qr[i] * kv.x;
                s[i][1] += qr[i] * kv.y;
                s[i][2] += qr[i] * kv.z;
                s[i][3] += qr[i] * kv.w;
            }
        }

#pragma unroll
        for (int i = 0; i < 8; i++) {
            float tm = fmaxf(fmaxf(s[i][0], s[i][1]), fmaxf(s[i][2], s[i][3]));
#pragma unroll
            for (int o = 1; o < 16; o <<= 1)
                tm = fmaxf(tm, __shfl_xor_sync(0xffffffffu, tm, o));
            float mn = fmaxf(m[i], tm);
            float corr = __expf(m[i] - mn);
            m[i] = mn;
            float rsum = 0.f;
#pragma unroll
            for (int j = 0; j < 4; j++) {
                s[i][j] = __expf(s[i][j] - mn);
                rsum += s[i][j];
            }
#pragma unroll
            for (int o = 1; o < 16; o <<= 1)
                rsum += __shfl_xor_sync(0xffffffffu, rsum, o);
            l[i] = l[i] * corr + rsum;
#pragma unroll
            for (int j = 0; j < 4; j++) Oa[i][j] *= corr;
        }

#pragma unroll
        for (int i = 0; i < 8; i++)
            *(float4*)(Ps + (ty * 8 + i) * ABN + tx * 4) =
                make_float4(s[i][0], s[i][1], s[i][2], s[i][3]);
        __syncthreads();

#pragma unroll 8
        for (int kk = 0; kk < ABN; kk++) {
            float4 vv = *(const float4*)(Vs + kk * 64 + tx * 4);
#pragma unroll
            for (int i = 0; i < 8; i++) {
                float p = Ps[(ty * 8 + i) * ABN + kk];
                Oa[i][0] += p * vv.x;
                Oa[i][1] += p * vv.y;
                Oa[i][2] += p * vv.z;
                Oa[i][3] += p * vv.w;
            }
        }
        __syncthreads();
    }

#pragma unroll
    for (int i = 0; i < 8; i++) {
        float inv = 1.0f / l[i];
        int row = q0 + ty * 8 + i;
        __half2 p0 = __floats2half2_rn(Oa[i][0] * inv, Oa[i][1] * inv);
        __half2 p1 = __floats2half2_rn(Oa[i][2] * inv, Oa[i][3] * inv);
        uint2 u;
        u.x = *(uint32_t*)&p0;
        u.y = *(uint32_t*)&p1;
        *(uint2*)(Oh + ((size_t)(b * S_LEN + row)) * DM + h * DKH + tx * 4) = u;
    }
}

// ---------------- launch ----------------
extern "C" void kernel_launch(void* const* d_in, const int* in_sizes, int n_in,
                              void* d_out, int out_size)
{
    const float* x    = (const float*)d_in[0];
    const float* Wq   = (const float*)d_in[1];
    const float* bq   = (const float*)d_in[2];
    const float* Wk   = (const float*)d_in[3];
    const float* bk   = (const float*)d_in[4];
    const float* Wv   = (const float*)d_in[5];
    const float* bv   = (const float*)d_in[6];
    const float* Wo   = (const float*)d_in[7];
    const float* bo   = (const float*)d_in[8];
    const float* W1   = (const float*)d_in[9];
    const float* b1   = (const float*)d_in[10];
    const float* W2   = (const float*)d_in[11];
    const float* b2   = (const float*)d_in[12];
    const float* ln1a = (const float*)d_in[13];
    const float* ln1b = (const float*)d_in[14];
    const float* ln2a = (const float*)d_in[15];
    const float* ln2b = (const float*)d_in[16];
    float* out = (float*)d_out;

    __half *p_n1h, *p_n1l, *p_aoh, *p_n2h, *p_n2l, *p_f1h;
    float *p_q, *p_k, *p_v, *p_h;
    __half *wqh, *wql, *wkh, *wkl, *wvh, *wvl, *woh, *wol, *w1h, *w1l, *w2h, *w2l;
    cudaGetSymbolAddress((void**)&p_n1h, g_n1h);
    cudaGetSymbolAddress((void**)&p_n1l, g_n1l);
    cudaGetSymbolAddress((void**)&p_q,  g_q);
    cudaGetSymbolAddress((void**)&p_k,  g_k);
    cudaGetSymbolAddress((void**)&p_v,  g_v);
    cudaGetSymbolAddress((void**)&p_aoh, g_aoh);
    cudaGetSymbolAddress((void**)&p_h,  g_h);
    cudaGetSymbolAddress((void**)&p_n2h, g_n2h);
    cudaGetSymbolAddress((void**)&p_n2l, g_n2l);
    cudaGetSymbolAddress((void**)&p_f1h, g_f1h);
    cudaGetSymbolAddress((void**)&wqh, g_wqh); cudaGetSymbolAddress((void**)&wql, g_wql);
    cudaGetSymbolAddress((void**)&wkh, g_wkh); cudaGetSymbolAddress((void**)&wkl, g_wkl);
    cudaGetSymbolAddress((void**)&wvh, g_wvh); cudaGetSymbolAddress((void**)&wvl, g_wvl);
    cudaGetSymbolAddress((void**)&woh, g_woh); cudaGetSymbolAddress((void**)&wol, g_wol);
    cudaGetSymbolAddress((void**)&w1h, g_w1h); cudaGetSymbolAddress((void**)&w1l, g_w1l);
    cudaGetSymbolAddress((void**)&w2h, g_w2h); cudaGetSymbolAddress((void**)&w2l, g_w2l);

    const int SMEM2 = 2 * 3 * 16384;   // 96KB (2-term, 2 stages)
    const int SMEM3 = 2 * 4 * 16384;   // 128KB (3-term, 2 stages)
    const int ATTN_SMEM = (64 * ABM + 64 * ABN + ABN * 64 + ABM * ABN) * 4;

    cudaFuncSetAttribute(fattn_kernel,
                         cudaFuncAttributeMaxDynamicSharedMemorySize, ATTN_SMEM);
    cudaFuncSetAttribute(tc2_gemm<3, false, false, false>,
                         cudaFuncAttributeMaxDynamicSharedMemorySize, SMEM3);
    cudaFuncSetAttribute(tc2_gemm<2, false, true, false>,
                         cudaFuncAttributeMaxDynamicSharedMemorySize, SMEM2);
    cudaFuncSetAttribute(tc2_gemm<2, true, false, true>,
                         cudaFuncAttributeMaxDynamicSharedMemorySize, SMEM2);

    // 0) weight transpose + split (cheap, graph-captured)
    wsplit_kernel<<<dim3(DM / 32, DM / 32), 256>>>(Wq, wqh, wql, DM, DM);
    wsplit_kernel<<<dim3(DM / 32, DM / 32), 256>>>(Wk, wkh, wkl, DM, DM);
    wsplit_kernel<<<dim3(DM / 32, DM / 32), 256>>>(Wv, wvh, wvl, DM, DM);
    wsplit_kernel<<<dim3(DM / 32, DM / 32), 256>>>(Wo, woh, wol, DM, DM);
    wsplit_kernel<<<dim3(DFF / 32, DM / 32), 256>>>(W1, w1h, w1l, DM, DFF);
    wsplit_kernel<<<dim3(DM / 32, DFF / 32), 256>>>(W2, w2h, w2l, DFF, DM);

    // 1) LN1 -> fp16 hi/lo
    ln_kernel<<<NTOK, 256>>>(x, ln1a, ln1b, p_n1h, p_n1l);

    // 2) Q/K/V projections (3-term: scores are precision-critical)
    dim3 gP(DM / GBN, NTOK / GBM);
    tc2_gemm<3, false, false, false><<<gP, 256, SMEM3>>>(
        p_n1h, p_n1l, wqh, wql, bq, nullptr, p_q, nullptr, NTOK, DM, DM);
    tc2_gemm<3, false, false, false><<<gP, 256, SMEM3>>>(
        p_n1h, p_n1l, wkh, wkl, bk, nullptr, p_k, nullptr, NTOK, DM, DM);
    tc2_gemm<3, false, false, false><<<gP, 256, SMEM3>>>(
        p_n1h, p_n1l, wvh, wvl, bv, nullptr, p_v, nullptr, NTOK, DM, DM);

    // 3) flash attention (fp32 internals, fp16 output)
    fattn_kernel<<<dim3(S_LEN / ABM, NHEAD, BATCH), 256, ATTN_SMEM>>>(
        p_q, p_k, p_v, p_aoh);

    // 4) output projection + residual(x) -> h fp32 (2-term)
    tc2_gemm<2, false, true, false><<<gP, 256, SMEM2>>>(
        p_aoh, nullptr, woh, wol, bo, x, p_h, nullptr, NTOK, DM, DM);

    // 5) LN2 -> fp16 (lo unused downstream but harmless)
    ln_kernel<<<NTOK, 256>>>(p_h, ln2a, ln2b, p_n2h, p_n2l);

    // 6) FFN up + ReLU -> f1 fp16 (2-term)
    tc2_gemm<2, true, false, true><<<dim3(DFF / GBN, NTOK / GBM), 256, SMEM2>>>(
        p_n2h, nullptr, w1h, w1l, b1, nullptr, nullptr, p_f1h, NTOK, DFF, DM);

    // 7) FFN down + residual(h) -> out fp32 (2-term)
    tc2_gemm<2, false, true, false><<<dim3(DM / GBN, NTOK / GBM), 256, SMEM2>>>(
        p_f1h, nullptr, w2h, w2l, b2, p_h, out, nullptr, NTOK, DM, DFF);
}

// round 6
// speedup vs baseline: 12.3049x; 1.7090x over previous
#include <cuda_runtime.h>
#include <cuda_fp16.h>
#include <math.h>
#include <cstdint>

#define S_LEN 2048
#define BATCH 2
#define DM    1024
#define NHEAD 16
#define DKH   64
#define DFF   4096
#define NTOK  (BATCH * S_LEN)   // 4096
#define LN_EPS 1e-6f

#define GBM 128
#define GBN 128
#define GBK 64

__device__ __forceinline__ uint32_t smem_u32(const void* p) {
    uint32_t a;
    asm("{ .reg .u64 t; cvta.to.shared.u64 t, %1; cvt.u32.u64 %0, t; }"
        : "=r"(a) : "l"(p));
    return a;
}
__device__ __forceinline__ void ldsm_x4(uint32_t addr, uint32_t& r0, uint32_t& r1,
                                        uint32_t& r2, uint32_t& r3) {
    asm volatile("ldmatrix.sync.aligned.m8n8.x4.shared.b16 {%0,%1,%2,%3}, [%4];"
                 : "=r"(r0), "=r"(r1), "=r"(r2), "=r"(r3) : "r"(addr));
}
__device__ __forceinline__ void mma_f16(float* c, uint32_t a0, uint32_t a1,
                                        uint32_t a2, uint32_t a3,
                                        uint32_t b0, uint32_t b1) {
    asm volatile(
        "mma.sync.aligned.m16n8k16.row.col.f32.f16.f16.f32 "
        "{%0,%1,%2,%3}, {%4,%5,%6,%7}, {%8,%9}, {%0,%1,%2,%3};"
        : "+f"(c[0]), "+f"(c[1]), "+f"(c[2]), "+f"(c[3])
        : "r"(a0), "r"(a1), "r"(a2), "r"(a3), "r"(b0), "r"(b1));
}
#define CP_ASYNC16(dst, src) \
    asm volatile("cp.async.cg.shared.global [%0], [%1], 16;" :: "r"(dst), "l"(src))
#define CP_COMMIT() asm volatile("cp.async.commit_group;" ::: "memory")
#define CP_WAIT0()  asm volatile("cp.async.wait_group 0;" ::: "memory")

// ---------------- scratch (device globals; no allocation) ----------------
__device__ __half g_n1h[NTOK * DM];
__device__ __half g_n1l[NTOK * DM];
__device__ __half g_qh[NTOK * DM], g_ql[NTOK * DM];
__device__ __half g_kh[NTOK * DM], g_kl[NTOK * DM];
__device__ __half g_vh[NTOK * DM];
__device__ __half g_aoh[NTOK * DM];
__device__ float  g_h [NTOK * DM];
__device__ __half g_n2h[NTOK * DM];
__device__ __half g_n2l[NTOK * DM];
__device__ __half g_f1h[NTOK * DFF];
// transposed split weights [N][K]
__device__ __half g_wqh[DM * DM],  g_wql[DM * DM];
__device__ __half g_wkh[DM * DM],  g_wkl[DM * DM];
__device__ __half g_wvh[DM * DM],  g_wvl[DM * DM];
__device__ __half g_woh[DM * DM],  g_wol[DM * DM];
__device__ __half g_w1h[DM * DFF], g_w1l[DM * DFF];
__device__ __half g_w2h[DFF * DM], g_w2l[DFF * DM];

// ---------------- weight transpose + fp16 hi/lo split ---------------------
__global__ void __launch_bounds__(256) wsplit_kernel(
    const float* __restrict__ W, __half* __restrict__ Bh, __half* __restrict__ Bl,
    int K, int N)
{
    __shared__ float tile[32][33];
    int n0 = blockIdx.x * 32, k0 = blockIdx.y * 32;
    int tx = threadIdx.x & 31, ty = threadIdx.x >> 5;
#pragma unroll
    for (int i = 0; i < 4; i++)
        tile[ty + 8 * i][tx] = W[(size_t)(k0 + ty + 8 * i) * N + n0 + tx];
    __syncthreads();
#pragma unroll
    for (int i = 0; i < 4; i++) {
        int nl = ty + 8 * i;
        float w = tile[tx][nl];
        __half h = __float2half_rn(w);
        __half l = __float2half_rn(w - __half2float(h));
        size_t o = (size_t)(n0 + nl) * K + k0 + tx;
        Bh[o] = h;
        Bl[o] = l;
    }
}

// ---------------- LayerNorm -> fp16 hi/lo ---------------------------------
__global__ void __launch_bounds__(256) ln_kernel(
    const float* __restrict__ x, const float* __restrict__ alpha,
    const float* __restrict__ beta, __half* __restrict__ yh,
    __half* __restrict__ yl)
{
    int row = blockIdx.x;
    int tid = threadIdx.x;
    const float4* x4 = (const float4*)(x + (size_t)row * DM);
    float4 v = x4[tid];
    float s = v.x + v.y + v.z + v.w;
    float q = v.x * v.x + v.y * v.y + v.z * v.z + v.w * v.w;

    __shared__ float rs[8], rq[8];
#pragma unroll
    for (int o = 16; o; o >>= 1) {
        s += __shfl_xor_sync(0xffffffffu, s, o);
        q += __shfl_xor_sync(0xffffffffu, q, o);
    }
    if ((tid & 31) == 0) { rs[tid >> 5] = s; rq[tid >> 5] = q; }
    __syncthreads();
    s = 0.f; q = 0.f;
#pragma unroll
    for (int i = 0; i < 8; i++) { s += rs[i]; q += rq[i]; }

    float mean = s * (1.0f / DM);
    float var  = (q - (float)DM * mean * mean) * (1.0f / (DM - 1));
    float a    = alpha[0];
    float b    = beta[0];
    float inv  = a / (sqrtf(var) + LN_EPS);

    float o0 = (v.x - mean) * inv + b;
    float o1 = (v.y - mean) * inv + b;
    float o2 = (v.z - mean) * inv + b;
    float o3 = (v.w - mean) * inv + b;

    __half2 h0 = __floats2half2_rn(o0, o1);
    __half2 h1 = __floats2half2_rn(o2, o3);
    float2 hf0 = __half22float2(h0), hf1 = __half22float2(h1);
    __half2 l0 = __floats2half2_rn(o0 - hf0.x, o1 - hf0.y);
    __half2 l1 = __floats2half2_rn(o2 - hf1.x, o3 - hf1.y);

    uint2 uh, ul;
    uh.x = *(uint32_t*)&h0; uh.y = *(uint32_t*)&h1;
    ul.x = *(uint32_t*)&l0; ul.y = *(uint32_t*)&l1;
    *(uint2*)(yh + (size_t)row * DM + tid * 4) = uh;
    *(uint2*)(yl + (size_t)row * DM + tid * 4) = ul;
}

// ---------------- HMMA GEMM (preconverted fp16, cp.async pipeline) --------
// C = A[M,K] @ B^T (B stored [N][K]) + bias (+res)(+relu)
// OUT: 0 = fp32, 1 = fp16, 2 = fp16 hi/lo pair
template<int TERMS, bool RELU, bool RES, int OUT>
__global__ void __launch_bounds__(256) tc2_gemm(
    const __half* __restrict__ Ah, const __half* __restrict__ Al,
    const __half* __restrict__ Bh, const __half* __restrict__ Bl,
    const float* __restrict__ bias, const float* __restrict__ res,
    float* __restrict__ Cf, __half* __restrict__ Ch, __half* __restrict__ Cl,
    int M, int N, int K)
{
    extern __shared__ char sm[];
    constexpr int TILES = (TERMS == 3) ? 4 : 3;
    constexpr uint32_t AH_OFF = 0;
    constexpr uint32_t AL_OFF = 16384;
    constexpr uint32_t BH_OFF = (TERMS == 3) ? 32768u : 16384u;
    constexpr uint32_t BL_OFF = BH_OFF + 16384u;
    const uint32_t STAGE = TILES * 16384u;

    const int tid = threadIdx.x;
    const int wid = tid >> 5;
    const int lid = tid & 31;
    const int nb = blockIdx.x, mb = blockIdx.y;

    const int warp_m = (wid >> 2) * 64;
    const int warp_n = (wid & 3) * 32;

    const uint32_t smb = smem_u32(sm);

    const int a_row = warp_m + (lid & 15);
    const uint32_t a_cb = (uint32_t)((lid >> 4) * 16);
    const int b_row_off = ((lid & 16) >> 1) + (lid & 7);
    const uint32_t b_cb = (lid & 8) ? 16u : 0u;
    const uint32_t xm = (uint32_t)((lid & 7) << 4);

    float acc[4][4][4];
#pragma unroll
    for (int i = 0; i < 4; i++)
#pragma unroll
        for (int j = 0; j < 4; j++)
#pragma unroll
            for (int r = 0; r < 4; r++) acc[i][j][r] = 0.f;

    const int sj = tid & 7;
    const int sr0 = tid >> 3;

    const int niter = K / GBK;

    auto stage = [&](int kt, int buf) {
        uint32_t base = smb + (uint32_t)buf * STAGE;
        const __half* aS = Ah + (size_t)(mb * GBM) * K + kt * GBK + sj * 8;
        const __half* bS = Bh + (size_t)(nb * GBN) * K + kt * GBK + sj * 8;
        const __half* blS = Bl + (size_t)(nb * GBN) * K + kt * GBK + sj * 8;
#pragma unroll
        for (int i = 0; i < 4; i++) {
            int r = i * 32 + sr0;
            uint32_t sw = (uint32_t)(r * 128 + ((sj * 16) ^ ((r & 7) << 4)));
            CP_ASYNC16(base + AH_OFF + sw, aS + (size_t)r * K);
            if (TERMS == 3)
                CP_ASYNC16(base + AL_OFF + sw, Al + (size_t)(mb * GBM + r) * K + kt * GBK + sj * 8);
            CP_ASYNC16(base + BH_OFF + sw, bS + (size_t)r * K);
            CP_ASYNC16(base + BL_OFF + sw, blS + (size_t)r * K);
        }
    };

    stage(0, 0);
    CP_COMMIT();

    for (int kt = 0; kt < niter; kt++) {
        int buf = kt & 1;
        CP_WAIT0();
        __syncthreads();
        if (kt + 1 < niter) {
            stage(kt + 1, buf ^ 1);
            CP_COMMIT();
        }

        uint32_t ah_u = smb + (uint32_t)buf * STAGE + AH_OFF;
        uint32_t al_u = smb + (uint32_t)buf * STAGE + AL_OFF;
        uint32_t bh_u = smb + (uint32_t)buf * STAGE + BH_OFF;
        uint32_t bl_u = smb + (uint32_t)buf * STAGE + BL_OFF;

#pragma unroll
        for (int s = 0; s < 4; s++) {
            uint32_t bhf[8], blf[8];
#pragma unroll
            for (int pr = 0; pr < 2; pr++) {
                uint32_t roff = (uint32_t)(warp_n + pr * 16 + b_row_off) * 128;
                uint32_t coff = (uint32_t)(s * 32 + b_cb) ^ xm;
                ldsm_x4(bh_u + roff + coff, bhf[pr*4+0], bhf[pr*4+1], bhf[pr*4+2], bhf[pr*4+3]);
                ldsm_x4(bl_u + roff + coff, blf[pr*4+0], blf[pr*4+1], blf[pr*4+2], blf[pr*4+3]);
            }
#pragma unroll
            for (int mt = 0; mt < 4; mt++) {
                uint32_t roff = (uint32_t)(a_row + mt * 16) * 128;
                uint32_t coff = (uint32_t)(s * 32 + a_cb) ^ xm;
                uint32_t a0, a1, a2, a3;
                ldsm_x4(ah_u + roff + coff, a0, a1, a2, a3);
                uint32_t l0 = 0, l1 = 0, l2 = 0, l3 = 0;
                if (TERMS == 3) ldsm_x4(al_u + roff + coff, l0, l1, l2, l3);
#pragma unroll
                for (int nt = 0; nt < 4; nt++) {
                    uint32_t hb0 = bhf[(nt >> 1) * 4 + (nt & 1) * 2];
                    uint32_t hb1 = bhf[(nt >> 1) * 4 + (nt & 1) * 2 + 1];
                    uint32_t lb0 = blf[(nt >> 1) * 4 + (nt & 1) * 2];
                    uint32_t lb1 = blf[(nt >> 1) * 4 + (nt & 1) * 2 + 1];
                    mma_f16(acc[mt][nt], a0, a1, a2, a3, hb0, hb1);
                    mma_f16(acc[mt][nt], a0, a1, a2, a3, lb0, lb1);
                    if (TERMS == 3)
                        mma_f16(acc[mt][nt], l0, l1, l2, l3, hb0, hb1);
                }
            }
        }
        __syncthreads();
    }

    // ---- epilogue ----
    {
        int g = lid >> 2, tig = lid & 3;
        int base_row = mb * GBM + warp_m + g;
        int base_col = nb * GBN + warp_n + tig * 2;
#pragma unroll
        for (int mt = 0; mt < 4; mt++) {
#pragma unroll
            for (int nt = 0; nt < 4; nt++) {
                int col = base_col + nt * 8;
                float2 bb = *(const float2*)(bias + col);
#pragma unroll
                for (int hrow = 0; hrow < 2; hrow++) {
                    int row = base_row + mt * 16 + hrow * 8;
                    float2 o;
                    o.x = acc[mt][nt][hrow * 2 + 0] + bb.x;
                    o.y = acc[mt][nt][hrow * 2 + 1] + bb.y;
                    if (RES) {
                        float2 r2 = *(const float2*)(res + (size_t)row * N + col);
                        o.x += r2.x; o.y += r2.y;
                    }
                    if (RELU) {
                        o.x = fmaxf(o.x, 0.f);
                        o.y = fmaxf(o.y, 0.f);
                    }
                    if (OUT == 0) {
                        *(float2*)(Cf + (size_t)row * N + col) = o;
                    } else if (OUT == 1) {
                        __half2 hv = __floats2half2_rn(o.x, o.y);
                        *(__half2*)(Ch + (size_t)row * N + col) = hv;
                    } else {
                        __half2 hv = __floats2half2_rn(o.x, o.y);
                        float2 hf = __half22float2(hv);
                        __half2 lv = __floats2half2_rn(o.x - hf.x, o.y - hf.y);
                        *(__half2*)(Ch + (size_t)row * N + col) = hv;
                        *(__half2*)(Cl + (size_t)row * N + col) = lv;
                    }
                }
            }
        }
    }
}

// ---------------- HMMA flash attention ------------------------------------
// Block: 256 thr (8 warps), 128 queries of one (b,h). Keys tiled by 64.
// Scores: 3-term fp16 split HMMA; softmax on fragments; P fp16; PV HMMA.
// smem: Qh[128][64] Ql KH[64][64] KL Vt[64(d)][64(key)] P[128][64], 128B rows SW128.
#define AQH 0u
#define AQL 16384u
#define AKH 32768u
#define AKL 40960u
#define AVT 49152u
#define APB 57344u
#define ATTN_SMEM 73728

__global__ void __launch_bounds__(256, 2) fattn_mma(
    const __half* __restrict__ Qh, const __half* __restrict__ Ql,
    const __half* __restrict__ Kh, const __half* __restrict__ Kl,
    const __half* __restrict__ Vh, __half* __restrict__ Oh)
{
    extern __shared__ char sm[];
    const uint32_t smb = smem_u32(sm);

    const int tid = threadIdx.x;
    const int wid = tid >> 5;
    const int lid = tid & 31;
    const int h = blockIdx.y, b = blockIdx.z;
    const int q0 = blockIdx.x * 128;

    const int warp_m = wid * 16;

    // ldmatrix addressing (validated layout)
    const int a_row = warp_m + (lid & 15);
    const uint32_t a_cb = (uint32_t)((lid >> 4) * 16);
    const int b_row_off = ((lid & 16) >> 1) + (lid & 7);
    const uint32_t b_cb = (lid & 8) ? 16u : 0u;
    const uint32_t xm = (uint32_t)((lid & 7) << 4);

    const size_t bh_off = ((size_t)b * S_LEN) * DM + h * DKH;

    // ---- stage Q tile (once): 128 rows x 8 chunks x2 arrays ----
    {
        int j = tid & 7;
        int r0 = tid >> 3;
#pragma unroll
        for (int i = 0; i < 4; i++) {
            int r = r0 + i * 32;
            uint32_t sw = (uint32_t)(r * 128 + ((j * 16) ^ ((r & 7) << 4)));
            const __half* qs = Qh + bh_off + (size_t)(q0 + r) * DM + j * 8;
            const __half* ls = Ql + bh_off + (size_t)(q0 + r) * DM + j * 8;
            CP_ASYNC16(smb + AQH + sw, qs);
            CP_ASYNC16(smb + AQL + sw, ls);
        }
        CP_COMMIT();
    }

    float Oa[8][4];
    float mrow[2], lrow[2];
#pragma unroll
    for (int nt = 0; nt < 8; nt++)
#pragma unroll
        for (int r = 0; r < 4; r++) Oa[nt][r] = 0.f;
    mrow[0] = mrow[1] = -INFINITY;
    lrow[0] = lrow[1] = 0.f;

    for (int k0 = 0; k0 < S_LEN; k0 += 64) {
        // ---- stage K tile (hi/lo, cp.async) ----
        {
            int j = tid & 7;
            int r0 = tid >> 3;
#pragma unroll
            for (int i = 0; i < 2; i++) {
                int r = r0 + i * 32;
                uint32_t sw = (uint32_t)(r * 128 + ((j * 16) ^ ((r & 7) << 4)));
                CP_ASYNC16(smb + AKH + sw, Kh + bh_off + (size_t)(k0 + r) * DM + j * 8);
                CP_ASYNC16(smb + AKL + sw, Kl + bh_off + (size_t)(k0 + r) * DM + j * 8);
            }
            CP_COMMIT();
        }
        // ---- stage V transposed: Vt[d][key] ----
        {
            int key = tid >> 2;
            int dc = (tid & 3) * 16;
            const __half* vsrc = Vh + bh_off + (size_t)(k0 + key) * DM + dc;
            uint4 u0 = *(const uint4*)(vsrc);
            uint4 u1 = *(const uint4*)(vsrc + 8);
            const __half* hv0 = (const __half*)&u0;
            const __half* hv1 = (const __half*)&u1;
#pragma unroll
            for (int dd = 0; dd < 8; dd++) {
                int d = dc + dd;
                uint32_t off = (uint32_t)(d * 128 + ((key * 2) ^ ((d & 7) << 4)));
                *(__half*)(sm + AVT + off) = hv0[dd];
            }
#pragma unroll
            for (int dd = 0; dd < 8; dd++) {
                int d = dc + 8 + dd;
                uint32_t off = (uint32_t)(d * 128 + ((key * 2) ^ ((d & 7) << 4)));
                *(__half*)(sm + AVT + off) = hv1[dd];
            }
        }
        CP_WAIT0();
        __syncthreads();

        // ---- phase A: S = Q K^T (3-term) ----
        float sacc[8][4];
#pragma unroll
        for (int nt = 0; nt < 8; nt++)
#pragma unroll
            for (int r = 0; r < 4; r++) sacc[nt][r] = 0.f;

#pragma unroll
        for (int s = 0; s < 4; s++) {
            uint32_t acoff = (uint32_t)(s * 32 + a_cb) ^ xm;
            uint32_t qa0, qa1, qa2, qa3, la0, la1, la2, la3;
            ldsm_x4(smb + AQH + (uint32_t)a_row * 128 + acoff, qa0, qa1, qa2, qa3);
            ldsm_x4(smb + AQL + (uint32_t)a_row * 128 + acoff, la0, la1, la2, la3);
            uint32_t bcoff = (uint32_t)(s * 32 + b_cb) ^ xm;
#pragma unroll
            for (int pr = 0; pr < 4; pr++) {
                uint32_t roff = (uint32_t)(pr * 16 + b_row_off) * 128;
                uint32_t h0, h1, h2, h3, l0, l1, l2, l3;
                ldsm_x4(smb + AKH + roff + bcoff, h0, h1, h2, h3);
                ldsm_x4(smb + AKL + roff + bcoff, l0, l1, l2, l3);
                mma_f16(sacc[pr*2+0], qa0, qa1, qa2, qa3, h0, h1);
                mma_f16(sacc[pr*2+0], qa0, qa1, qa2, qa3, l0, l1);
                mma_f16(sacc[pr*2+0], la0, la1, la2, la3, h0, h1);
                mma_f16(sacc[pr*2+1], qa0, qa1, qa2, qa3, h2, h3);
                mma_f16(sacc[pr*2+1], qa0, qa1, qa2, qa3, l2, l3);
                mma_f16(sacc[pr*2+1], la0, la1, la2, la3, h2, h3);
            }
        }

        // ---- online softmax on fragments ----
        float corr0, corr1;
        {
#pragma unroll
            for (int r = 0; r < 2; r++) {
                float mx = -INFINITY;
#pragma unroll
                for (int nt = 0; nt < 8; nt++) {
                    mx = fmaxf(mx, sacc[nt][r*2+0]);
                    mx = fmaxf(mx, sacc[nt][r*2+1]);
                }
                mx = fmaxf(mx, __shfl_xor_sync(0xffffffffu, mx, 1));
                mx = fmaxf(mx, __shfl_xor_sync(0xffffffffu, mx, 2));
                float mn = fmaxf(mrow[r], mx);
                float c = __expf(mrow[r] - mn);
                mrow[r] = mn;
                float sum = 0.f;
#pragma unroll
                for (int nt = 0; nt < 8; nt++) {
                    float e0 = __expf(sacc[nt][r*2+0] - mn);
                    float e1 = __expf(sacc[nt][r*2+1] - mn);
                    sacc[nt][r*2+0] = e0;
                    sacc[nt][r*2+1] = e1;
                    sum += e0 + e1;
                }
                sum += __shfl_xor_sync(0xffffffffu, sum, 1);
                sum += __shfl_xor_sync(0xffffffffu, sum, 2);
                lrow[r] = lrow[r] * c + sum;
                if (r == 0) corr0 = c; else corr1 = c;
            }
#pragma unroll
            for (int nt = 0; nt < 8; nt++) {
                Oa[nt][0] *= corr0; Oa[nt][1] *= corr0;
                Oa[nt][2] *= corr1; Oa[nt][3] *= corr1;
            }
        }

        // ---- store P fp16 to smem ----
        {
            int g = lid >> 2, tig = lid & 3;
            int row0 = warp_m + g;
            int row1 = row0 + 8;
            uint32_t x0 = (uint32_t)((row0 & 7) << 4);
            uint32_t x1 = (uint32_t)((row1 & 7) << 4);
#pragma unroll
            for (int nt = 0; nt < 8; nt++) {
                int col = tig * 2 + nt * 8;
                __half2 p0 = __floats2half2_rn(sacc[nt][0], sacc[nt][1]);
                __half2 p1 = __floats2half2_rn(sacc[nt][2], sacc[nt][3]);
                *(__half2*)(sm + APB + (uint32_t)(row0 * 128 + ((col * 2) ^ x0))) = p0;
                *(__half2*)(sm + APB + (uint32_t)(row1 * 128 + ((col * 2) ^ x1))) = p1;
            }
        }
        __syncthreads();

        // ---- phase B: O += P Vt^T ----
#pragma unroll
        for (int s = 0; s < 4; s++) {
            uint32_t acoff = (uint32_t)(s * 32 + a_cb) ^ xm;
            uint32_t pa0, pa1, pa2, pa3;
            ldsm_x4(smb + APB + (uint32_t)a_row * 128 + acoff, pa0, pa1, pa2, pa3);
            uint32_t bcoff = (uint32_t)(s * 32 + b_cb) ^ xm;
#pragma unroll
            for (int pr = 0; pr < 4; pr++) {
                uint32_t roff = (uint32_t)(pr * 16 + b_row_off) * 128;
                uint32_t v0, v1, v2, v3;
                ldsm_x4(smb + AVT + roff + bcoff, v0, v1, v2, v3);
                mma_f16(Oa[pr*2+0], pa0, pa1, pa2, pa3, v0, v1);
                mma_f16(Oa[pr*2+1], pa0, pa1, pa2, pa3, v2, v3);
            }
        }
        __syncthreads();
    }

    // ---- epilogue: O / l -> fp16 ----
    {
        int g = lid >> 2, tig = lid & 3;
        float inv0 = 1.0f / lrow[0];
        float inv1 = 1.0f / lrow[1];
        int row0 = q0 + warp_m + g;
        int row1 = row0 + 8;
#pragma unroll
        for (int nt = 0; nt < 8; nt++) {
            int col = tig * 2 + nt * 8;
            __half2 o0 = __floats2half2_rn(Oa[nt][0] * inv0, Oa[nt][1] * inv0);
            __half2 o1 = __floats2half2_rn(Oa[nt][2] * inv1, Oa[nt][3] * inv1);
            *(__half2*)(Oh + bh_off + (size_t)row0 * DM + col) = o0;
            *(__half2*)(Oh + bh_off + (size_t)row1 * DM + col) = o1;
        }
    }
}

// ---------------- launch ----------------
extern "C" void kernel_launch(void* const* d_in, const int* in_sizes, int n_in,
                              void* d_out, int out_size)
{
    const float* x    = (const float*)d_in[0];
    const float* Wq   = (const float*)d_in[1];
    const float* bq   = (const float*)d_in[2];
    const float* Wk   = (const float*)d_in[3];
    const float* bk   = (const float*)d_in[4];
    const float* Wv   = (const float*)d_in[5];
    const float* bv   = (const float*)d_in[6];
    const float* Wo   = (const float*)d_in[7];
    const float* bo   = (const float*)d_in[8];
    const float* W1   = (const float*)d_in[9];
    const float* b1   = (const float*)d_in[10];
    const float* W2   = (const float*)d_in[11];
    const float* b2   = (const float*)d_in[12];
    const float* ln1a = (const float*)d_in[13];
    const float* ln1b = (const float*)d_in[14];
    const float* ln2a = (const float*)d_in[15];
    const float* ln2b = (const float*)d_in[16];
    float* out = (float*)d_out;

    __half *p_n1h, *p_n1l, *p_qh, *p_ql, *p_kh, *p_kl, *p_vh;
    __half *p_aoh, *p_n2h, *p_n2l, *p_f1h;
    float *p_h;
    __half *wqh, *wql, *wkh, *wkl, *wvh, *wvl, *woh, *wol, *w1h, *w1l, *w2h, *w2l;
    cudaGetSymbolAddress((void**)&p_n1h, g_n1h);
    cudaGetSymbolAddress((void**)&p_n1l, g_n1l);
    cudaGetSymbolAddress((void**)&p_qh, g_qh);
    cudaGetSymbolAddress((void**)&p_ql, g_ql);
    cudaGetSymbolAddress((void**)&p_kh, g_kh);
    cudaGetSymbolAddress((void**)&p_kl, g_kl);
    cudaGetSymbolAddress((void**)&p_vh, g_vh);
    cudaGetSymbolAddress((void**)&p_aoh, g_aoh);
    cudaGetSymbolAddress((void**)&p_h,  g_h);
    cudaGetSymbolAddress((void**)&p_n2h, g_n2h);
    cudaGetSymbolAddress((void**)&p_n2l, g_n2l);
    cudaGetSymbolAddress((void**)&p_f1h, g_f1h);
    cudaGetSymbolAddress((void**)&wqh, g_wqh); cudaGetSymbolAddress((void**)&wql, g_wql);
    cudaGetSymbolAddress((void**)&wkh, g_wkh); cudaGetSymbolAddress((void**)&wkl, g_wkl);
    cudaGetSymbolAddress((void**)&wvh, g_wvh); cudaGetSymbolAddress((void**)&wvl, g_wvl);
    cudaGetSymbolAddress((void**)&woh, g_woh); cudaGetSymbolAddress((void**)&wol, g_wol);
    cudaGetSymbolAddress((void**)&w1h, g_w1h); cudaGetSymbolAddress((void**)&w1l, g_w1l);
    cudaGetSymbolAddress((void**)&w2h, g_w2h); cudaGetSymbolAddress((void**)&w2l, g_w2l);

    const int SMEM2 = 2 * 3 * 16384;
    const int SMEM3 = 2 * 4 * 16384;

    cudaFuncSetAttribute(fattn_mma,
                         cudaFuncAttributeMaxDynamicSharedMemorySize, ATTN_SMEM);
    cudaFuncSetAttribute(tc2_gemm<3, false, false, 2>,
                         cudaFuncAttributeMaxDynamicSharedMemorySize, SMEM3);
    cudaFuncSetAttribute(tc2_gemm<3, false, false, 1>,
                         cudaFuncAttributeMaxDynamicSharedMemorySize, SMEM3);
    cudaFuncSetAttribute(tc2_gemm<2, false, true, 0>,
                         cudaFuncAttributeMaxDynamicSharedMemorySize, SMEM2);
    cudaFuncSetAttribute(tc2_gemm<2, true, false, 1>,
                         cudaFuncAttributeMaxDynamicSharedMemorySize, SMEM2);

    // 0) weight transpose + split
    wsplit_kernel<<<dim3(DM / 32, DM / 32), 256>>>(Wq, wqh, wql, DM, DM);
    wsplit_kernel<<<dim3(DM / 32, DM / 32), 256>>>(Wk, wkh, wkl, DM, DM);
    wsplit_kernel<<<dim3(DM / 32, DM / 32), 256>>>(Wv, wvh, wvl, DM, DM);
    wsplit_kernel<<<dim3(DM / 32, DM / 32), 256>>>(Wo, woh, wol, DM, DM);
    wsplit_kernel<<<dim3(DFF / 32, DM / 32), 256>>>(W1, w1h, w1l, DM, DFF);
    wsplit_kernel<<<dim3(DM / 32, DFF / 32), 256>>>(W2, w2h, w2l, DFF, DM);

    // 1) LN1 -> fp16 hi/lo
    ln_kernel<<<NTOK, 256>>>(x, ln1a, ln1b, p_n1h, p_n1l);

    // 2) Q/K/V projections (3-term; Q,K hi/lo out, V fp16 out)
    dim3 gP(DM / GBN, NTOK / GBM);
    tc2_gemm<3, false, false, 2><<<gP, 256, SMEM3>>>(
        p_n1h, p_n1l, wqh, wql, bq, nullptr, nullptr, p_qh, p_ql, NTOK, DM, DM);
    tc2_gemm<3, false, false, 2><<<gP, 256, SMEM3>>>(
        p_n1h, p_n1l, wkh, wkl, bk, nullptr, nullptr, p_kh, p_kl, NTOK, DM, DM);
    tc2_gemm<3, false, false, 1><<<gP, 256, SMEM3>>>(
        p_n1h, p_n1l, wvh, wvl, bv, nullptr, nullptr, p_vh, nullptr, NTOK, DM, DM);

    // 3) HMMA flash attention (no 1/sqrt(dk) scaling, per reference)
    fattn_mma<<<dim3(S_LEN / 128, NHEAD, BATCH), 256, ATTN_SMEM>>>(
        p_qh, p_ql, p_kh, p_kl, p_vh, p_aoh);

    // 4) output projection + residual(x) -> h fp32 (2-term)
    tc2_gemm<2, false, true, 0><<<gP, 256, SMEM2>>>(
        p_aoh, nullptr, woh, wol, bo, x, p_h, nullptr, nullptr, NTOK, DM, DM);

    // 5) LN2 -> fp16
    ln_kernel<<<NTOK, 256>>>(p_h, ln2a, ln2b, p_n2h, p_n2l);

    // 6) FFN up + ReLU -> f1 fp16 (2-term)
    tc2_gemm<2, true, false, 1><<<dim3(DFF / GBN, NTOK / GBM), 256, SMEM2>>>(
        p_n2h, nullptr, w1h, w1l, b1, nullptr, nullptr, p_f1h, nullptr, NTOK, DFF, DM);

    // 7) FFN down + residual(h) -> out fp32 (2-term)
    tc2_gemm<2, false, true, 0><<<dim3(DM / GBN, NTOK / GBM), 256, SMEM2>>>(
        p_f1h, nullptr, w2h, w2l, b2, p_h, out, nullptr, nullptr, NTOK, DM, DFF);
}

// round 7
// speedup vs baseline: 13.7334x; 1.1161x over previous
#include <cuda_runtime.h>
#include <cuda_fp16.h>
#include <math.h>
#include <cstdint>

#define S_LEN 2048
#define BATCH 2
#define DM    1024
#define NHEAD 16
#define DKH   64
#define DFF   4096
#define NTOK  (BATCH * S_LEN)   // 4096
#define LN_EPS 1e-6f

#define GBM 128
#define GBN 128
#define GBK 64

__device__ __forceinline__ uint32_t smem_u32(const void* p) {
    uint32_t a;
    asm("{ .reg .u64 t; cvta.to.shared.u64 t, %1; cvt.u32.u64 %0, t; }"
        : "=r"(a) : "l"(p));
    return a;
}
__device__ __forceinline__ void ldsm_x4(uint32_t addr, uint32_t& r0, uint32_t& r1,
                                        uint32_t& r2, uint32_t& r3) {
    asm volatile("ldmatrix.sync.aligned.m8n8.x4.shared.b16 {%0,%1,%2,%3}, [%4];"
                 : "=r"(r0), "=r"(r1), "=r"(r2), "=r"(r3) : "r"(addr));
}
__device__ __forceinline__ void ldsm_x4_t(uint32_t addr, uint32_t& r0, uint32_t& r1,
                                          uint32_t& r2, uint32_t& r3) {
    asm volatile("ldmatrix.sync.aligned.m8n8.x4.trans.shared.b16 {%0,%1,%2,%3}, [%4];"
                 : "=r"(r0), "=r"(r1), "=r"(r2), "=r"(r3) : "r"(addr));
}
__device__ __forceinline__ void mma_f16(float* c, uint32_t a0, uint32_t a1,
                                        uint32_t a2, uint32_t a3,
                                        uint32_t b0, uint32_t b1) {
    asm volatile(
        "mma.sync.aligned.m16n8k16.row.col.f32.f16.f16.f32 "
        "{%0,%1,%2,%3}, {%4,%5,%6,%7}, {%8,%9}, {%0,%1,%2,%3};"
        : "+f"(c[0]), "+f"(c[1]), "+f"(c[2]), "+f"(c[3])
        : "r"(a0), "r"(a1), "r"(a2), "r"(a3), "r"(b0), "r"(b1));
}
#define CP_ASYNC16(dst, src) \
    asm volatile("cp.async.cg.shared.global [%0], [%1], 16;" :: "r"(dst), "l"(src))
#define CP_COMMIT() asm volatile("cp.async.commit_group;" ::: "memory")
#define CP_WAIT0()  asm volatile("cp.async.wait_group 0;" ::: "memory")

// ---------------- scratch (device globals; no allocation) ----------------
__device__ __half g_n1h[NTOK * DM];
__device__ __half g_n1l[NTOK * DM];
__device__ __half g_qh[NTOK * DM], g_ql[NTOK * DM];
__device__ __half g_kh[NTOK * DM], g_kl[NTOK * DM];
__device__ __half g_vh[NTOK * DM];
__device__ __half g_aoh[NTOK * DM];
__device__ float  g_h [NTOK * DM];
__device__ __half g_n2h[NTOK * DM];
__device__ __half g_n2l[NTOK * DM];
__device__ __half g_f1h[NTOK * DFF];
// transposed split weights [N][K]; qkv concatenated [3072][1024]
__device__ __half g_wqkvh[3 * DM * DM], g_wqkvl[3 * DM * DM];
__device__ __half g_woh[DM * DM],  g_wol[DM * DM];
__device__ __half g_w1h[DM * DFF], g_w1l[DM * DFF];
__device__ __half g_w2h[DFF * DM], g_w2l[DFF * DM];

// ---------------- weight transpose + fp16 hi/lo split ---------------------
__global__ void __launch_bounds__(256) wsplit_kernel(
    const float* __restrict__ W, __half* __restrict__ Bh, __half* __restrict__ Bl,
    int K, int N)
{
    __shared__ float tile[32][33];
    int n0 = blockIdx.x * 32, k0 = blockIdx.y * 32;
    int tx = threadIdx.x & 31, ty = threadIdx.x >> 5;
#pragma unroll
    for (int i = 0; i < 4; i++)
        tile[ty + 8 * i][tx] = W[(size_t)(k0 + ty + 8 * i) * N + n0 + tx];
    __syncthreads();
#pragma unroll
    for (int i = 0; i < 4; i++) {
        int nl = ty + 8 * i;
        float w = tile[tx][nl];
        __half h = __float2half_rn(w);
        __half l = __float2half_rn(w - __half2float(h));
        size_t o = (size_t)(n0 + nl) * K + k0 + tx;
        Bh[o] = h;
        Bl[o] = l;
    }
}

// ---------------- LayerNorm -> fp16 hi/lo ---------------------------------
__global__ void __launch_bounds__(256) ln_kernel(
    const float* __restrict__ x, const float* __restrict__ alpha,
    const float* __restrict__ beta, __half* __restrict__ yh,
    __half* __restrict__ yl)
{
    int row = blockIdx.x;
    int tid = threadIdx.x;
    const float4* x4 = (const float4*)(x + (size_t)row * DM);
    float4 v = x4[tid];
    float s = v.x + v.y + v.z + v.w;
    float q = v.x * v.x + v.y * v.y + v.z * v.z + v.w * v.w;

    __shared__ float rs[8], rq[8];
#pragma unroll
    for (int o = 16; o; o >>= 1) {
        s += __shfl_xor_sync(0xffffffffu, s, o);
        q += __shfl_xor_sync(0xffffffffu, q, o);
    }
    if ((tid & 31) == 0) { rs[tid >> 5] = s; rq[tid >> 5] = q; }
    __syncthreads();
    s = 0.f; q = 0.f;
#pragma unroll
    for (int i = 0; i < 8; i++) { s += rs[i]; q += rq[i]; }

    float mean = s * (1.0f / DM);
    float var  = (q - (float)DM * mean * mean) * (1.0f / (DM - 1));
    float a    = alpha[0];
    float b    = beta[0];
    float inv  = a / (sqrtf(var) + LN_EPS);

    float o0 = (v.x - mean) * inv + b;
    float o1 = (v.y - mean) * inv + b;
    float o2 = (v.z - mean) * inv + b;
    float o3 = (v.w - mean) * inv + b;

    __half2 h0 = __floats2half2_rn(o0, o1);
    __half2 h1 = __floats2half2_rn(o2, o3);
    float2 hf0 = __half22float2(h0), hf1 = __half22float2(h1);
    __half2 l0 = __floats2half2_rn(o0 - hf0.x, o1 - hf0.y);
    __half2 l1 = __floats2half2_rn(o2 - hf1.x, o3 - hf1.y);

    uint2 uh, ul;
    uh.x = *(uint32_t*)&h0; uh.y = *(uint32_t*)&h1;
    ul.x = *(uint32_t*)&l0; ul.y = *(uint32_t*)&l1;
    *(uint2*)(yh + (size_t)row * DM + tid * 4) = uh;
    *(uint2*)(yl + (size_t)row * DM + tid * 4) = ul;
}

// ---------------- 2-term HMMA GEMM (Wo / FFN) -----------------------------
// C = A[M,K] @ B^T (B stored [N][K]) + bias (+res)(+relu); OUT: 0 fp32, 1 fp16
template<bool RELU, bool RES, int OUT>
__global__ void __launch_bounds__(256, 2) tc2_gemm(
    const __half* __restrict__ Ah,
    const __half* __restrict__ Bh, const __half* __restrict__ Bl,
    const float* __restrict__ bias, const float* __restrict__ res,
    float* __restrict__ Cf, __half* __restrict__ Ch,
    int M, int N, int K)
{
    extern __shared__ char sm[];
    constexpr uint32_t AH_OFF = 0;
    constexpr uint32_t BH_OFF = 16384u;
    constexpr uint32_t BL_OFF = 32768u;
    const uint32_t STAGE = 3 * 16384u;

    const int tid = threadIdx.x;
    const int wid = tid >> 5;
    const int lid = tid & 31;
    const int nb = blockIdx.x, mb = blockIdx.y;

    const int warp_m = (wid >> 2) * 64;
    const int warp_n = (wid & 3) * 32;

    const uint32_t smb = smem_u32(sm);

    const int a_row = warp_m + (lid & 15);
    const uint32_t a_cb = (uint32_t)((lid >> 4) * 16);
    const int b_row_off = ((lid & 16) >> 1) + (lid & 7);
    const uint32_t b_cb = (lid & 8) ? 16u : 0u;
    const uint32_t xm = (uint32_t)((lid & 7) << 4);

    float acc[4][4][4];
#pragma unroll
    for (int i = 0; i < 4; i++)
#pragma unroll
        for (int j = 0; j < 4; j++)
#pragma unroll
            for (int r = 0; r < 4; r++) acc[i][j][r] = 0.f;

    const int sj = tid & 7;
    const int sr0 = tid >> 3;
    const int niter = K / GBK;

    auto stage = [&](int kt, int buf) {
        uint32_t base = smb + (uint32_t)buf * STAGE;
#pragma unroll
        for (int i = 0; i < 4; i++) {
            int r = i * 32 + sr0;
            uint32_t sw = (uint32_t)(r * 128 + ((sj * 16) ^ ((r & 7) << 4)));
            CP_ASYNC16(base + AH_OFF + sw, Ah + (size_t)(mb * GBM + r) * K + kt * GBK + sj * 8);
            CP_ASYNC16(base + BH_OFF + sw, Bh + (size_t)(nb * GBN + r) * K + kt * GBK + sj * 8);
            CP_ASYNC16(base + BL_OFF + sw, Bl + (size_t)(nb * GBN + r) * K + kt * GBK + sj * 8);
        }
    };

    stage(0, 0);
    CP_COMMIT();

    for (int kt = 0; kt < niter; kt++) {
        int buf = kt & 1;
        CP_WAIT0();
        __syncthreads();
        if (kt + 1 < niter) {
            stage(kt + 1, buf ^ 1);
            CP_COMMIT();
        }

        uint32_t ah_u = smb + (uint32_t)buf * STAGE + AH_OFF;
        uint32_t bh_u = smb + (uint32_t)buf * STAGE + BH_OFF;
        uint32_t bl_u = smb + (uint32_t)buf * STAGE + BL_OFF;

#pragma unroll
        for (int s = 0; s < 4; s++) {
            uint32_t bhf[8], blf[8];
#pragma unroll
            for (int pr = 0; pr < 2; pr++) {
                uint32_t roff = (uint32_t)(warp_n + pr * 16 + b_row_off) * 128;
                uint32_t coff = (uint32_t)(s * 32 + b_cb) ^ xm;
                ldsm_x4(bh_u + roff + coff, bhf[pr*4+0], bhf[pr*4+1], bhf[pr*4+2], bhf[pr*4+3]);
                ldsm_x4(bl_u + roff + coff, blf[pr*4+0], blf[pr*4+1], blf[pr*4+2], blf[pr*4+3]);
            }
#pragma unroll
            for (int mt = 0; mt < 4; mt++) {
                uint32_t roff = (uint32_t)(a_row + mt * 16) * 128;
                uint32_t coff = (uint32_t)(s * 32 + a_cb) ^ xm;
                uint32_t a0, a1, a2, a3;
                ldsm_x4(ah_u + roff + coff, a0, a1, a2, a3);
#pragma unroll
                for (int nt = 0; nt < 4; nt++) {
                    uint32_t hb0 = bhf[(nt >> 1) * 4 + (nt & 1) * 2];
                    uint32_t hb1 = bhf[(nt >> 1) * 4 + (nt & 1) * 2 + 1];
                    uint32_t lb0 = blf[(nt >> 1) * 4 + (nt & 1) * 2];
                    uint32_t lb1 = blf[(nt >> 1) * 4 + (nt & 1) * 2 + 1];
                    mma_f16(acc[mt][nt], a0, a1, a2, a3, hb0, hb1);
                    mma_f16(acc[mt][nt], a0, a1, a2, a3, lb0, lb1);
                }
            }
        }
        __syncthreads();
    }

    {
        int g = lid >> 2, tig = lid & 3;
        int base_row = mb * GBM + warp_m + g;
        int base_col = nb * GBN + warp_n + tig * 2;
#pragma unroll
        for (int mt = 0; mt < 4; mt++) {
#pragma unroll
            for (int nt = 0; nt < 4; nt++) {
                int col = base_col + nt * 8;
                float2 bb = *(const float2*)(bias + col);
#pragma unroll
                for (int hrow = 0; hrow < 2; hrow++) {
                    int row = base_row + mt * 16 + hrow * 8;
                    float2 o;
                    o.x = acc[mt][nt][hrow * 2 + 0] + bb.x;
                    o.y = acc[mt][nt][hrow * 2 + 1] + bb.y;
                    if (RES) {
                        float2 r2 = *(const float2*)(res + (size_t)row * N + col);
                        o.x += r2.x; o.y += r2.y;
                    }
                    if (RELU) {
                        o.x = fmaxf(o.x, 0.f);
                        o.y = fmaxf(o.y, 0.f);
                    }
                    if (OUT == 0) {
                        *(float2*)(Cf + (size_t)row * N + col) = o;
                    } else {
                        __half2 hv = __floats2half2_rn(o.x, o.y);
                        *(__half2*)(Ch + (size_t)row * N + col) = hv;
                    }
                }
            }
        }
    }
}

// ---------------- fused QKV 3-term GEMM -----------------------------------
// A = n1 hi/lo, B = concat(Wq,Wk,Wv) hi/lo [3072][1024].
// Epilogue: section 0 -> Q hi/lo, 1 -> K hi/lo, 2 -> V fp16.
__global__ void __launch_bounds__(256) tc_qkv_gemm(
    const __half* __restrict__ Ah, const __half* __restrict__ Al,
    const __half* __restrict__ Bh, const __half* __restrict__ Bl,
    const float* __restrict__ bq, const float* __restrict__ bk,
    const float* __restrict__ bv,
    __half* __restrict__ Qh, __half* __restrict__ Ql,
    __half* __restrict__ Kh, __half* __restrict__ Kl,
    __half* __restrict__ Vh)
{
    extern __shared__ char sm[];
    constexpr uint32_t AH_OFF = 0;
    constexpr uint32_t AL_OFF = 16384u;
    constexpr uint32_t BH_OFF = 32768u;
    constexpr uint32_t BL_OFF = 49152u;
    const uint32_t STAGE = 4 * 16384u;
    const int K = DM, NW = 3 * DM;

    const int tid = threadIdx.x;
    const int wid = tid >> 5;
    const int lid = tid & 31;
    const int nb = blockIdx.x, mb = blockIdx.y;

    const int warp_m = (wid >> 2) * 64;
    const int warp_n = (wid & 3) * 32;

    const uint32_t smb = smem_u32(sm);

    const int a_row = warp_m + (lid & 15);
    const uint32_t a_cb = (uint32_t)((lid >> 4) * 16);
    const int b_row_off = ((lid & 16) >> 1) + (lid & 7);
    const uint32_t b_cb = (lid & 8) ? 16u : 0u;
    const uint32_t xm = (uint32_t)((lid & 7) << 4);

    float acc[4][4][4];
#pragma unroll
    for (int i = 0; i < 4; i++)
#pragma unroll
        for (int j = 0; j < 4; j++)
#pragma unroll
            for (int r = 0; r < 4; r++) acc[i][j][r] = 0.f;

    const int sj = tid & 7;
    const int sr0 = tid >> 3;
    const int niter = K / GBK;

    auto stage = [&](int kt, int buf) {
        uint32_t base = smb + (uint32_t)buf * STAGE;
#pragma unroll
        for (int i = 0; i < 4; i++) {
            int r = i * 32 + sr0;
            uint32_t sw = (uint32_t)(r * 128 + ((sj * 16) ^ ((r & 7) << 4)));
            CP_ASYNC16(base + AH_OFF + sw, Ah + (size_t)(mb * GBM + r) * K + kt * GBK + sj * 8);
            CP_ASYNC16(base + AL_OFF + sw, Al + (size_t)(mb * GBM + r) * K + kt * GBK + sj * 8);
            CP_ASYNC16(base + BH_OFF + sw, Bh + (size_t)(nb * GBN + r) * K + kt * GBK + sj * 8);
            CP_ASYNC16(base + BL_OFF + sw, Bl + (size_t)(nb * GBN + r) * K + kt * GBK + sj * 8);
        }
    };

    stage(0, 0);
    CP_COMMIT();

    for (int kt = 0; kt < niter; kt++) {
        int buf = kt & 1;
        CP_WAIT0();
        __syncthreads();
        if (kt + 1 < niter) {
            stage(kt + 1, buf ^ 1);
            CP_COMMIT();
        }

        uint32_t ah_u = smb + (uint32_t)buf * STAGE + AH_OFF;
        uint32_t al_u = smb + (uint32_t)buf * STAGE + AL_OFF;
        uint32_t bh_u = smb + (uint32_t)buf * STAGE + BH_OFF;
        uint32_t bl_u = smb + (uint32_t)buf * STAGE + BL_OFF;

#pragma unroll
        for (int s = 0; s < 4; s++) {
            uint32_t bhf[8], blf[8];
#pragma unroll
            for (int pr = 0; pr < 2; pr++) {
                uint32_t roff = (uint32_t)(warp_n + pr * 16 + b_row_off) * 128;
                uint32_t coff = (uint32_t)(s * 32 + b_cb) ^ xm;
                ldsm_x4(bh_u + roff + coff, bhf[pr*4+0], bhf[pr*4+1], bhf[pr*4+2], bhf[pr*4+3]);
                ldsm_x4(bl_u + roff + coff, blf[pr*4+0], blf[pr*4+1], blf[pr*4+2], blf[pr*4+3]);
            }
#pragma unroll
            for (int mt = 0; mt < 4; mt++) {
                uint32_t roff = (uint32_t)(a_row + mt * 16) * 128;
                uint32_t coff = (uint32_t)(s * 32 + a_cb) ^ xm;
                uint32_t a0, a1, a2, a3, l0, l1, l2, l3;
                ldsm_x4(ah_u + roff + coff, a0, a1, a2, a3);
                ldsm_x4(al_u + roff + coff, l0, l1, l2, l3);
#pragma unroll
                for (int nt = 0; nt < 4; nt++) {
                    uint32_t hb0 = bhf[(nt >> 1) * 4 + (nt & 1) * 2];
                    uint32_t hb1 = bhf[(nt >> 1) * 4 + (nt & 1) * 2 + 1];
                    uint32_t lb0 = blf[(nt >> 1) * 4 + (nt & 1) * 2];
                    uint32_t lb1 = blf[(nt >> 1) * 4 + (nt & 1) * 2 + 1];
                    mma_f16(acc[mt][nt], a0, a1, a2, a3, hb0, hb1);
                    mma_f16(acc[mt][nt], a0, a1, a2, a3, lb0, lb1);
                    mma_f16(acc[mt][nt], l0, l1, l2, l3, hb0, hb1);
                }
            }
        }
        __syncthreads();
    }

    // ---- epilogue: route by section ----
    {
        int sect = nb >> 3;                 // 0=Q, 1=K, 2=V
        int nb_l = nb & 7;
        const float* bp = (sect == 0) ? bq : ((sect == 1) ? bk : bv);
        __half* Dh = (sect == 0) ? Qh : ((sect == 1) ? Kh : Vh);
        __half* Dl = (sect == 0) ? Ql : Kl;

        int g = lid >> 2, tig = lid & 3;
        int base_row = mb * GBM + warp_m + g;
        int base_col = nb_l * GBN + warp_n + tig * 2;
#pragma unroll
        for (int mt = 0; mt < 4; mt++) {
#pragma unroll
            for (int nt = 0; nt < 4; nt++) {
                int col = base_col + nt * 8;
                float2 bb = *(const float2*)(bp + col);
#pragma unroll
                for (int hrow = 0; hrow < 2; hrow++) {
                    int row = base_row + mt * 16 + hrow * 8;
                    float ox = acc[mt][nt][hrow * 2 + 0] + bb.x;
                    float oy = acc[mt][nt][hrow * 2 + 1] + bb.y;
                    __half2 hv = __floats2half2_rn(ox, oy);
                    *(__half2*)(Dh + (size_t)row * DM + col) = hv;
                    if (sect < 2) {
                        float2 hf = __half22float2(hv);
                        __half2 lv = __floats2half2_rn(ox - hf.x, oy - hf.y);
                        *(__half2*)(Dl + (size_t)row * DM + col) = lv;
                    }
                }
            }
        }
    }
}

// ---------------- HMMA flash attention (double-buffered K/V, trans-V) -----
// smem: Q hi/lo 32KB | 2 x (KH 8 + KL 8 + VS 8) = 48KB | P 16KB = 96KB
#define AQH 0u
#define AQL 16384u
#define ABUF0 32768u
#define ABUFSZ 24576u
#define APB 81920u
#define ATTN_SMEM 98304

__global__ void __launch_bounds__(256, 2) fattn_mma(
    const __half* __restrict__ Qh, const __half* __restrict__ Ql,
    const __half* __restrict__ Kh, const __half* __restrict__ Kl,
    const __half* __restrict__ Vh, __half* __restrict__ Oh)
{
    extern __shared__ char sm[];
    const uint32_t smb = smem_u32(sm);

    const int tid = threadIdx.x;
    const int wid = tid >> 5;
    const int lid = tid & 31;
    const int h = blockIdx.y, b = blockIdx.z;
    const int q0 = blockIdx.x * 128;

    const int warp_m = wid * 16;

    const int a_row = warp_m + (lid & 15);
    const uint32_t a_cb = (uint32_t)((lid >> 4) * 16);
    const int b_row_off = ((lid & 16) >> 1) + (lid & 7);
    const uint32_t b_cb = (lid & 8) ? 16u : 0u;
    const uint32_t xm = (uint32_t)((lid & 7) << 4);

    // trans-V lane addressing
    const int v_krow = lid & 15;
    const uint32_t v_db = (uint32_t)((lid >> 4) << 4);

    const size_t bh_off = ((size_t)b * S_LEN) * DM + h * DKH;

    const int sj = tid & 7;
    const int sr0 = tid >> 3;

    // ---- stage Q (once) ----
    {
#pragma unroll
        for (int i = 0; i < 4; i++) {
            int r = sr0 + i * 32;
            uint32_t sw = (uint32_t)(r * 128 + ((sj * 16) ^ ((r & 7) << 4)));
            CP_ASYNC16(smb + AQH + sw, Qh + bh_off + (size_t)(q0 + r) * DM + sj * 8);
            CP_ASYNC16(smb + AQL + sw, Ql + bh_off + (size_t)(q0 + r) * DM + sj * 8);
        }
        CP_COMMIT();
    }

    auto stage_kv = [&](int k0, int buf) {
        uint32_t base = smb + ABUF0 + (uint32_t)buf * ABUFSZ;
#pragma unroll
        for (int i = 0; i < 2; i++) {
            int r = sr0 + i * 32;
            uint32_t sw = (uint32_t)(r * 128 + ((sj * 16) ^ ((r & 7) << 4)));
            CP_ASYNC16(base + sw,          Kh + bh_off + (size_t)(k0 + r) * DM + sj * 8);
            CP_ASYNC16(base + 8192u + sw,  Kl + bh_off + (size_t)(k0 + r) * DM + sj * 8);
            CP_ASYNC16(base + 16384u + sw, Vh + bh_off + (size_t)(k0 + r) * DM + sj * 8);
        }
    };

    stage_kv(0, 0);
    CP_COMMIT();

    float Oa[8][4];
    float mrow[2], lrow[2];
#pragma unroll
    for (int nt = 0; nt < 8; nt++)
#pragma unroll
        for (int r = 0; r < 4; r++) Oa[nt][r] = 0.f;
    mrow[0] = mrow[1] = -INFINITY;
    lrow[0] = lrow[1] = 0.f;

    CP_WAIT0();
    __syncthreads();

    const int NT = S_LEN / 64;
    for (int t = 0; t < NT; t++) {
        int buf = t & 1;
        uint32_t kh_u = smb + ABUF0 + (uint32_t)buf * ABUFSZ;
        uint32_t kl_u = kh_u + 8192u;
        uint32_t vs_u = kh_u + 16384u;

        if (t + 1 < NT) {
            stage_kv((t + 1) * 64, buf ^ 1);
            CP_COMMIT();
        }

        // ---- phase A: S = Q K^T (3-term) ----
        float sacc[8][4];
#pragma unroll
        for (int nt = 0; nt < 8; nt++)
#pragma unroll
            for (int r = 0; r < 4; r++) sacc[nt][r] = 0.f;

#pragma unroll
        for (int s = 0; s < 4; s++) {
            uint32_t acoff = (uint32_t)(s * 32 + a_cb) ^ xm;
            uint32_t qa0, qa1, qa2, qa3, la0, la1, la2, la3;
            ldsm_x4(smb + AQH + (uint32_t)a_row * 128 + acoff, qa0, qa1, qa2, qa3);
            ldsm_x4(smb + AQL + (uint32_t)a_row * 128 + acoff, la0, la1, la2, la3);
            uint32_t bcoff = (uint32_t)(s * 32 + b_cb) ^ xm;
#pragma unroll
            for (int pr = 0; pr < 4; pr++) {
                uint32_t roff = (uint32_t)(pr * 16 + b_row_off) * 128;
                uint32_t h0, h1, h2, h3, l0, l1, l2, l3;
                ldsm_x4(kh_u + roff + bcoff, h0, h1, h2, h3);
                ldsm_x4(kl_u + roff + bcoff, l0, l1, l2, l3);
                mma_f16(sacc[pr*2+0], qa0, qa1, qa2, qa3, h0, h1);
                mma_f16(sacc[pr*2+0], qa0, qa1, qa2, qa3, l0, l1);
                mma_f16(sacc[pr*2+0], la0, la1, la2, la3, h0, h1);
                mma_f16(sacc[pr*2+1], qa0, qa1, qa2, qa3, h2, h3);
                mma_f16(sacc[pr*2+1], qa0, qa1, qa2, qa3, l2, l3);
                mma_f16(sacc[pr*2+1], la0, la1, la2, la3, h2, h3);
            }
        }

        // ---- online softmax on fragments ----
        float corr0, corr1;
#pragma unroll
        for (int r = 0; r < 2; r++) {
            float mx = -INFINITY;
#pragma unroll
            for (int nt = 0; nt < 8; nt++) {
                mx = fmaxf(mx, sacc[nt][r*2+0]);
                mx = fmaxf(mx, sacc[nt][r*2+1]);
            }
            mx = fmaxf(mx, __shfl_xor_sync(0xffffffffu, mx, 1));
            mx = fmaxf(mx, __shfl_xor_sync(0xffffffffu, mx, 2));
            float mn = fmaxf(mrow[r], mx);
            float c = __expf(mrow[r] - mn);
            mrow[r] = mn;
            float sum = 0.f;
#pragma unroll
            for (int nt = 0; nt < 8; nt++) {
                float e0 = __expf(sacc[nt][r*2+0] - mn);
                float e1 = __expf(sacc[nt][r*2+1] - mn);
                sacc[nt][r*2+0] = e0;
                sacc[nt][r*2+1] = e1;
                sum += e0 + e1;
            }
            sum += __shfl_xor_sync(0xffffffffu, sum, 1);
            sum += __shfl_xor_sync(0xffffffffu, sum, 2);
            lrow[r] = lrow[r] * c + sum;
            if (r == 0) corr0 = c; else corr1 = c;
        }
#pragma unroll
        for (int nt = 0; nt < 8; nt++) {
            Oa[nt][0] *= corr0; Oa[nt][1] *= corr0;
            Oa[nt][2] *= corr1; Oa[nt][3] *= corr1;
        }

        // ---- store P fp16 (per-warp rows; warp-local dependency) ----
        __syncwarp();
        {
            int g = lid >> 2, tig = lid & 3;
            int row0 = warp_m + g;
            int row1 = row0 + 8;
            uint32_t x0 = (uint32_t)((row0 & 7) << 4);
            uint32_t x1 = (uint32_t)((row1 & 7) << 4);
#pragma unroll
            for (int nt = 0; nt < 8; nt++) {
                int col = tig * 2 + nt * 8;
                __half2 p0 = __floats2half2_rn(sacc[nt][0], sacc[nt][1]);
                __half2 p1 = __floats2half2_rn(sacc[nt][2], sacc[nt][3]);
                *(__half2*)(sm + APB + (uint32_t)(row0 * 128 + ((col * 2) ^ x0))) = p0;
                *(__half2*)(sm + APB + (uint32_t)(row1 * 128 + ((col * 2) ^ x1))) = p1;
            }
        }
        __syncwarp();

        // ---- phase B: O += P @ V (V rows staged direct, trans ldmatrix) --
#pragma unroll
        for (int s = 0; s < 4; s++) {
            uint32_t acoff = (uint32_t)(s * 32 + a_cb) ^ xm;
            uint32_t pa0, pa1, pa2, pa3;
            ldsm_x4(smb + APB + (uint32_t)a_row * 128 + acoff, pa0, pa1, pa2, pa3);
            int krow = s * 16 + v_krow;
#pragma unroll
            for (int pr = 0; pr < 4; pr++) {
                uint32_t vaddr = vs_u + (uint32_t)krow * 128 +
                                 (((uint32_t)(pr * 32) + v_db) ^ ((uint32_t)(krow & 7) << 4));
                uint32_t v0, v1, v2, v3;
                ldsm_x4_t(vaddr, v0, v1, v2, v3);
                mma_f16(Oa[pr*2+0], pa0, pa1, pa2, pa3, v0, v1);
                mma_f16(Oa[pr*2+1], pa0, pa1, pa2, pa3, v2, v3);
            }
        }

        if (t + 1 < NT) CP_WAIT0();
        __syncthreads();
    }

    // ---- epilogue ----
    {
        int g = lid >> 2, tig = lid & 3;
        float inv0 = 1.0f / lrow[0];
        float inv1 = 1.0f / lrow[1];
        int row0 = q0 + warp_m + g;
        int row1 = row0 + 8;
#pragma unroll
        for (int nt = 0; nt < 8; nt++) {
            int col = tig * 2 + nt * 8;
            __half2 o0 = __floats2half2_rn(Oa[nt][0] * inv0, Oa[nt][1] * inv0);
            __half2 o1 = __floats2half2_rn(Oa[nt][2] * inv1, Oa[nt][3] * inv1);
            *(__half2*)(Oh + bh_off + (size_t)row0 * DM + col) = o0;
            *(__half2*)(Oh + bh_off + (size_t)row1 * DM + col) = o1;
        }
    }
}

// ---------------- launch ----------------
extern "C" void kernel_launch(void* const* d_in, const int* in_sizes, int n_in,
                              void* d_out, int out_size)
{
    const float* x    = (const float*)d_in[0];
    const float* Wq   = (const float*)d_in[1];
    const float* bq   = (const float*)d_in[2];
    const float* Wk   = (const float*)d_in[3];
    const float* bk   = (const float*)d_in[4];
    const float* Wv   = (const float*)d_in[5];
    const float* bv   = (const float*)d_in[6];
    const float* Wo   = (const float*)d_in[7];
    const float* bo   = (const float*)d_in[8];
    const float* W1   = (const float*)d_in[9];
    const float* b1   = (const float*)d_in[10];
    const float* W2   = (const float*)d_in[11];
    const float* b2   = (const float*)d_in[12];
    const float* ln1a = (const float*)d_in[13];
    const float* ln1b = (const float*)d_in[14];
    const float* ln2a = (const float*)d_in[15];
    const float* ln2b = (const float*)d_in[16];
    float* out = (float*)d_out;

    __half *p_n1h, *p_n1l, *p_qh, *p_ql, *p_kh, *p_kl, *p_vh;
    __half *p_aoh, *p_n2h, *p_n2l, *p_f1h;
    float *p_h;
    __half *wqkvh, *wqkvl, *woh, *wol, *w1h, *w1l, *w2h, *w2l;
    cudaGetSymbolAddress((void**)&p_n1h, g_n1h);
    cudaGetSymbolAddress((void**)&p_n1l, g_n1l);
    cudaGetSymbolAddress((void**)&p_qh, g_qh);
    cudaGetSymbolAddress((void**)&p_ql, g_ql);
    cudaGetSymbolAddress((void**)&p_kh, g_kh);
    cudaGetSymbolAddress((void**)&p_kl, g_kl);
    cudaGetSymbolAddress((void**)&p_vh, g_vh);
    cudaGetSymbolAddress((void**)&p_aoh, g_aoh);
    cudaGetSymbolAddress((void**)&p_h,  g_h);
    cudaGetSymbolAddress((void**)&p_n2h, g_n2h);
    cudaGetSymbolAddress((void**)&p_n2l, g_n2l);
    cudaGetSymbolAddress((void**)&p_f1h, g_f1h);
    cudaGetSymbolAddress((void**)&wqkvh, g_wqkvh);
    cudaGetSymbolAddress((void**)&wqkvl, g_wqkvl);
    cudaGetSymbolAddress((void**)&woh, g_woh); cudaGetSymbolAddress((void**)&wol, g_wol);
    cudaGetSymbolAddress((void**)&w1h, g_w1h); cudaGetSymbolAddress((void**)&w1l, g_w1l);
    cudaGetSymbolAddress((void**)&w2h, g_w2h); cudaGetSymbolAddress((void**)&w2l, g_w2l);

    const int SMEM2 = 2 * 3 * 16384;   // 96KB
    const int SMEM3 = 2 * 4 * 16384;   // 128KB

    cudaFuncSetAttribute(fattn_mma,
                         cudaFuncAttributeMaxDynamicSharedMemorySize, ATTN_SMEM);
    cudaFuncSetAttribute(tc_qkv_gemm,
                         cudaFuncAttributeMaxDynamicSharedMemorySize, SMEM3);
    cudaFuncSetAttribute(tc2_gemm<false, true, 0>,
                         cudaFuncAttributeMaxDynamicSharedMemorySize, SMEM2);
    cudaFuncSetAttribute(tc2_gemm<true, false, 1>,
                         cudaFuncAttributeMaxDynamicSharedMemorySize, SMEM2);

    // 0) weight transpose + split (qkv concatenated)
    wsplit_kernel<<<dim3(DM / 32, DM / 32), 256>>>(Wq, wqkvh, wqkvl, DM, DM);
    wsplit_kernel<<<dim3(DM / 32, DM / 32), 256>>>(Wk, wqkvh + DM * DM, wqkvl + DM * DM, DM, DM);
    wsplit_kernel<<<dim3(DM / 32, DM / 32), 256>>>(Wv, wqkvh + 2 * DM * DM, wqkvl + 2 * DM * DM, DM, DM);
    wsplit_kernel<<<dim3(DM / 32, DM / 32), 256>>>(Wo, woh, wol, DM, DM);
    wsplit_kernel<<<dim3(DFF / 32, DM / 32), 256>>>(W1, w1h, w1l, DM, DFF);
    wsplit_kernel<<<dim3(DM / 32, DFF / 32), 256>>>(W2, w2h, w2l, DFF, DM);

    // 1) LN1 -> fp16 hi/lo
    ln_kernel<<<NTOK, 256>>>(x, ln1a, ln1b, p_n1h, p_n1l);

    // 2) fused QKV projection (3-term; Q,K hi/lo out, V fp16 out)
    tc_qkv_gemm<<<dim3(3 * DM / GBN, NTOK / GBM), 256, SMEM3>>>(
        p_n1h, p_n1l, wqkvh, wqkvl, bq, bk, bv,
        p_qh, p_ql, p_kh, p_kl, p_vh);

    // 3) HMMA flash attention (no 1/sqrt(dk) scaling, per reference)
    fattn_mma<<<dim3(S_LEN / 128, NHEAD, BATCH), 256, ATTN_SMEM>>>(
        p_qh, p_ql, p_kh, p_kl, p_vh, p_aoh);

    // 4) output projection + residual(x) -> h fp32 (2-term)
    dim3 gP(DM / GBN, NTOK / GBM);
    tc2_gemm<false, true, 0><<<gP, 256, SMEM2>>>(
        p_aoh, woh, wol, bo, x, p_h, nullptr, NTOK, DM, DM);

    // 5) LN2 -> fp16
    ln_kernel<<<NTOK, 256>>>(p_h, ln2a, ln2b, p_n2h, p_n2l);

    // 6) FFN up + ReLU -> f1 fp16 (2-term)
    tc2_gemm<true, false, 1><<<dim3(DFF / GBN, NTOK / GBM), 256, SMEM2>>>(
        p_n2h, w1h, w1l, b1, nullptr, nullptr, p_f1h, NTOK, DFF, DM);

    // 7) FFN down + residual(h) -> out fp32 (2-term)
    tc2_gemm<false, true, 0><<<dim3(DM / GBN, NTOK / GBM), 256, SMEM2>>>(
        p_f1h, w2h, w2l, b2, p_h, out, nullptr, NTOK, DM, DFF);
}